// round 9
// baseline (speedup 1.0000x reference)
#include <cuda_runtime.h>
#include <cuda_fp16.h>
#include <cstdint>

// ---------------- problem constants ----------------
#define B_SZ     16384
#define NNEIGH   7
#define HDIM     512
#define HDIM2    256                   // HDIM in half2/float2 units
#define MROWS    (B_SZ * NNEIGH)      // 114688
#define SELF_W   18
#define NEIGH_W  6
#define OBS_W    (SELF_W + NEIGH_W * NNEIGH)  // 60
#define NGROUPS  (B_SZ / 8)           // 2048
#define OUT_HALF ((size_t)B_SZ * HDIM)

// GEMM tiling (128x64 tile, 3 CTAs/SM)
#define BM   128
#define BN   64
#define BKH  64                        // halves per K chunk (128 bytes/row)
#define NCHUNK (HDIM / BKH)            // 8
#define TILE_A (BM * 128)              // 16384 B
#define TILE_B (BN * 128)              // 8192 B
#define STAGE_BYTES (TILE_A + TILE_B)  // 24576
#define STAGES 3
#define GEMM_SMEM (STAGES * STAGE_BYTES)  // 72KB

// ---------------- scratch (__device__ globals; no allocs allowed) ---------
__device__ __half g_h1h[(size_t)MROWS * HDIM];
__device__ __half g_Eh [(size_t)MROWS * HDIM];
__device__ __half g_Vh [(size_t)MROWS * HDIM];
__device__ __half g_aah[(size_t)B_SZ * HDIM];
__device__ __half g_ahh[(size_t)B_SZ * HDIM];
__device__ __half g_avh[(size_t)B_SZ * HDIM];
__device__ __half g_Wt [5 * (size_t)HDIM * HDIM];
__device__ __half g_Wt1[(size_t)HDIM * 32];     // W_e1^T padded to K=32

// ---------------- small helpers ----------------
__device__ __forceinline__ uint32_t smem_u32(const void* p) {
    uint32_t a;
    asm("{ .reg .u64 t; cvta.to.shared.u64 t, %1; cvt.u32.u64 %0, t; }" : "=r"(a) : "l"(p));
    return a;
}
__device__ __forceinline__ void cp16(uint32_t s, const void* g) {
    asm volatile("cp.async.cg.shared.global [%0], [%1], 16;" :: "r"(s), "l"(g));
}
#define CP_COMMIT()  asm volatile("cp.async.commit_group;" ::: "memory")
#define CP_WAIT(n)   asm volatile("cp.async.wait_group %0;" :: "n"(n) : "memory")

__device__ __forceinline__ void ldmx4(uint32_t addr, uint32_t* r) {
    asm volatile("ldmatrix.sync.aligned.m8n8.x4.shared.b16 {%0,%1,%2,%3}, [%4];"
        : "=r"(r[0]), "=r"(r[1]), "=r"(r[2]), "=r"(r[3]) : "r"(addr));
}
__device__ __forceinline__ void mma16816(float* c, const uint32_t* a, uint32_t b0, uint32_t b1) {
    asm volatile("mma.sync.aligned.m16n8k16.row.col.f32.f16.f16.f32 "
        "{%0,%1,%2,%3},{%4,%5,%6,%7},{%8,%9},{%0,%1,%2,%3};"
        : "+f"(c[0]), "+f"(c[1]), "+f"(c[2]), "+f"(c[3])
        : "r"(a[0]), "r"(a[1]), "r"(a[2]), "r"(a[3]), "r"(b0), "r"(b1));
}
__device__ __forceinline__ uint32_t sw128(uint32_t off) {   // SW128 swizzle
    return off ^ ((off >> 3) & 0x70);
}
// single-MUFU tanh (sm_75+); max rel err ~2^-11 == fp16 quantization scale
__device__ __forceinline__ float ftanh(float x) {
    float r;
    asm("tanh.approx.f32 %0, %1;" : "=f"(r) : "f"(x));
    return r;
}

// =====================================================================
// Weight prep: 5 transposes (z=0..4) + W_e1 pad/transpose (z=5)
// =====================================================================
__global__ __launch_bounds__(256) void prep_weights_kernel(
    const float* __restrict__ W0, const float* __restrict__ W1,
    const float* __restrict__ W2, const float* __restrict__ W3,
    const float* __restrict__ W4, __half* __restrict__ WtBase,
    const float* __restrict__ We1, __half* __restrict__ Wt1)
{
    __shared__ float t[32][33];
    if (blockIdx.z == 5) {
        const int ftid = threadIdx.y * 32 + threadIdx.x;
        const int idx = (blockIdx.y * 16 + blockIdx.x) * 256 + ftid;
        if (idx < HDIM * 32) {
            const int n = idx >> 5, k = idx & 31;
            Wt1[idx] = (k < 24) ? __float2half(We1[(size_t)k * HDIM + n]) : __half(0.f);
        }
        return;
    }
    const float* W;
    switch (blockIdx.z) {
        case 0: W = W0; break;
        case 1: W = W1; break;
        case 2: W = W2; break;
        case 3: W = W3; break;
        default: W = W4; break;
    }
    __half* Wt = WtBase + (size_t)blockIdx.z * HDIM * HDIM;
    const int bx = blockIdx.x * 32, by = blockIdx.y * 32;
    #pragma unroll
    for (int i = threadIdx.y; i < 32; i += 8)
        t[i][threadIdx.x] = W[(size_t)(by + i) * HDIM + bx + threadIdx.x];
    __syncthreads();
    #pragma unroll
    for (int i = threadIdx.y; i < 32; i += 8)
        Wt[(size_t)(bx + i) * HDIM + by + threadIdx.x] = __float2half(t[threadIdx.x][i]);
}

// =====================================================================
// Kernel 1: fused gather + HMMA GEMM (K=24 pad 32) + bias + tanh -> fp16
//   (tile 128x128, single chunk; unchanged from R7)
// =====================================================================
__global__ __launch_bounds__(256) void embed1_hmma(
    const float* __restrict__ self_obs, const float* __restrict__ obs,
    const __half* __restrict__ Wt1, const float* __restrict__ bias,
    __half* __restrict__ C)
{
    __shared__ __align__(128) unsigned char sm[2 * 16384];  // A, B (128 rows x 128B)
    const uint32_t sbase = smem_u32(sm);
    const int tid  = threadIdx.x;
    const int wid  = tid >> 5, lane = tid & 31;
    const int n0   = blockIdx.x * 128;
    const int m0   = blockIdx.y * BM;
    const int wm   = (wid >> 2) * 64;
    const int wn   = (wid & 3) * 32;

    // ---- fill tiles: each thread 1 half-row (32B = 16 halves) ----
    const int row = tid >> 1, seg = tid & 1;
    {
        const int j = m0 + row;
        const int sb = (j % B_SZ) * SELF_W;
        const int ob = (j / NNEIGH) * OBS_W + SELF_W + (j % NNEIGH) * NEIGH_W;
        __half vals[16];
        #pragma unroll
        for (int c = 0; c < 16; c++) {
            const int k = seg * 16 + c;
            float v = 0.f;
            if (k < SELF_W)      v = __ldg(self_obs + sb + k);
            else if (k < 24)     v = __ldg(obs + ob + (k - SELF_W));
            vals[c] = __float2half(v);
        }
        const uint32_t base = (uint32_t)row * 128 + (uint32_t)seg * 32;
        *(uint4*)(sm + sw128(base))      = ((const uint4*)vals)[0];
        *(uint4*)(sm + sw128(base + 16)) = ((const uint4*)vals)[1];
        const __half* bsrc = Wt1 + (size_t)(n0 + row) * 32 + seg * 16;
        *(uint4*)(sm + 16384 + sw128(base))      = *(const uint4*)bsrc;
        *(uint4*)(sm + 16384 + sw128(base + 16)) = *(const uint4*)(bsrc + 8);
    }
    __syncthreads();

    const int arow = wm + ((lane >> 3) & 1) * 8 + (lane & 7);
    const uint32_t acolbase = ((lane >> 4) & 1) * 16;
    const int brow = wn + ((lane >> 4) & 1) * 8 + (lane & 7);
    const uint32_t bcolbase = ((lane >> 3) & 1) * 16;

    float acc[4][4][4];
    #pragma unroll
    for (int mt = 0; mt < 4; mt++)
        #pragma unroll
        for (int nt = 0; nt < 4; nt++)
            #pragma unroll
            for (int e = 0; e < 4; e++) acc[mt][nt][e] = 0.f;

    const uint32_t sA = sbase, sB = sbase + 16384;
    #pragma unroll
    for (int ks = 0; ks < 2; ks++) {
        uint32_t bf[2][4];
        #pragma unroll
        for (int g = 0; g < 2; g++) {
            int r = brow + g * 16;
            uint32_t col = (bcolbase + ks * 32) ^ (((uint32_t)(r & 7)) << 4);
            ldmx4(sB + (uint32_t)r * 128 + col, bf[g]);
        }
        uint32_t af[4];
        #pragma unroll
        for (int mt = 0; mt < 4; mt++) {
            int r = arow + mt * 16;
            uint32_t col = (acolbase + ks * 32) ^ (((uint32_t)(r & 7)) << 4);
            ldmx4(sA + (uint32_t)r * 128 + col, af);
            #pragma unroll
            for (int g = 0; g < 2; g++) {
                mma16816(acc[mt][2 * g],     af, bf[g][0], bf[g][1]);
                mma16816(acc[mt][2 * g + 1], af, bf[g][2], bf[g][3]);
            }
        }
    }

    const int qrow = lane >> 2;
    const int qcol = (lane & 3) * 2;
    #pragma unroll
    for (int mt = 0; mt < 4; mt++) {
        const size_t r0 = (size_t)(m0 + wm + mt * 16 + qrow) * HDIM;
        const size_t r1 = r0 + 8 * HDIM;
        #pragma unroll
        for (int nt = 0; nt < 4; nt++) {
            const int col = n0 + wn + nt * 8 + qcol;
            const float b0 = __ldg(bias + col), b1 = __ldg(bias + col + 1);
            *(__half2*)(C + r0 + col) =
                __floats2half2_rn(ftanh(acc[mt][nt][0] + b0), ftanh(acc[mt][nt][1] + b1));
            *(__half2*)(C + r1 + col) =
                __floats2half2_rn(ftanh(acc[mt][nt][2] + b0), ftanh(acc[mt][nt][3] + b1));
        }
    }
}

// =====================================================================
// Kernel 2: HMMA fp16 GEMM, tile 128x64, warp tile 32x32, 3 CTAs/SM
//   C = (half) tanh(A @ Wt^T + bias); grid (8, m_blocks)
// =====================================================================
__global__ __launch_bounds__(256, 3) void gemm_hmma(
    const __half* __restrict__ A, const __half* __restrict__ Wt,
    const float* __restrict__ bias, __half* __restrict__ C)
{
    extern __shared__ __align__(16) unsigned char smem[];
    const uint32_t sbase = smem_u32(smem);
    const int tid  = threadIdx.x;
    const int wid  = tid >> 5, lane = tid & 31;
    const int n0   = blockIdx.x * BN;
    const int m0   = blockIdx.y * BM;
    const int wm   = (wid >> 1) * 32;      // 0,32,64,96
    const int wn   = (wid & 1) * 32;       // 0,32

    // ---- cp.async loader mapping: rows lrow + i*32, seg lseg (16B) ----
    const int lrow = tid >> 3, lseg = tid & 7;
    const uint32_t swb = (uint32_t)lrow * 128 + (uint32_t)lseg * 16;
    const __half* gA = A  + (size_t)(m0 + lrow) * HDIM + lseg * 8;
    const __half* gB = Wt + (size_t)(n0 + lrow) * HDIM + lseg * 8;

    // ---- hoisted ldmatrix address components ----
    const int arow = wm + ((lane >> 3) & 1) * 8 + (lane & 7);
    const uint32_t mA = ((uint32_t)(arow & 7)) << 4;
    const uint32_t acb = (((lane >> 4) & 1) * 16) ^ (mA & 16u);
    const int brow = wn + ((lane >> 4) & 1) * 8 + (lane & 7);
    const uint32_t mB = ((uint32_t)(brow & 7)) << 4;
    const uint32_t bcb = (((lane >> 3) & 1) * 16) ^ (mB & 16u);
    uint32_t aoff[2], boff[2], ksoA[4], ksoB[4];
    #pragma unroll
    for (int mt = 0; mt < 2; mt++) aoff[mt] = (uint32_t)(arow + mt * 16) * 128 + acb;
    #pragma unroll
    for (int g = 0; g < 2; g++)    boff[g]  = (uint32_t)(brow + g * 16) * 128 + bcb + TILE_A;
    #pragma unroll
    for (int ks = 0; ks < 4; ks++) {
        ksoA[ks] = ((uint32_t)(ks * 32)) ^ (mA & 0x60u);
        ksoB[ks] = ((uint32_t)(ks * 32)) ^ (mB & 0x60u);
    }

    float acc[2][4][4];
    #pragma unroll
    for (int mt = 0; mt < 2; mt++)
        #pragma unroll
        for (int nt = 0; nt < 4; nt++)
            #pragma unroll
            for (int e = 0; e < 4; e++) acc[mt][nt][e] = 0.f;

    // ---- prologue: stages 0,1 ----
    #pragma unroll
    for (int s = 0; s < 2; s++) {
        const uint32_t dst = sbase + s * STAGE_BYTES;
        #pragma unroll
        for (int i = 0; i < 4; i++)
            cp16(dst + sw128(swb + (uint32_t)i * 32 * 128),
                 gA + s * BKH + (size_t)i * 32 * HDIM);
        #pragma unroll
        for (int i = 0; i < 2; i++)
            cp16(dst + TILE_A + sw128(swb + (uint32_t)i * 32 * 128),
                 gB + s * BKH + (size_t)i * 32 * HDIM);
        CP_COMMIT();
    }

    uint32_t cstage = 0, lstage = 2;
    #pragma unroll 1
    for (int c = 0; c < NCHUNK; c++) {
        CP_WAIT(1);
        __syncthreads();
        if (c + 2 < NCHUNK) {
            const uint32_t dst = sbase + lstage * STAGE_BYTES;
            #pragma unroll
            for (int i = 0; i < 4; i++)
                cp16(dst + sw128(swb + (uint32_t)i * 32 * 128),
                     gA + (c + 2) * BKH + (size_t)i * 32 * HDIM);
            #pragma unroll
            for (int i = 0; i < 2; i++)
                cp16(dst + TILE_A + sw128(swb + (uint32_t)i * 32 * 128),
                     gB + (c + 2) * BKH + (size_t)i * 32 * HDIM);
            if (++lstage == STAGES) lstage = 0;
        }
        CP_COMMIT();

        const uint32_t sS = sbase + cstage * STAGE_BYTES;
        #pragma unroll
        for (int ks = 0; ks < 4; ks++) {
            uint32_t bf[2][4], af[2][4];
            ldmx4(sS + boff[0] + ksoB[ks], bf[0]);
            ldmx4(sS + boff[1] + ksoB[ks], bf[1]);
            ldmx4(sS + aoff[0] + ksoA[ks], af[0]);
            ldmx4(sS + aoff[1] + ksoA[ks], af[1]);
            #pragma unroll
            for (int mt = 0; mt < 2; mt++) {
                #pragma unroll
                for (int g = 0; g < 2; g++) {
                    mma16816(acc[mt][2 * g],     af[mt], bf[g][0], bf[g][1]);
                    mma16816(acc[mt][2 * g + 1], af[mt], bf[g][2], bf[g][3]);
                }
            }
        }
        if (++cstage == STAGES) cstage = 0;
    }

    // ---- epilogue: bias + tanh.approx -> fp16 ----
    const int qrow = lane >> 2;
    const int qcol = (lane & 3) * 2;
    #pragma unroll
    for (int mt = 0; mt < 2; mt++) {
        const size_t r0 = (size_t)(m0 + wm + mt * 16 + qrow) * HDIM;
        const size_t r1 = r0 + 8 * HDIM;
        #pragma unroll
        for (int nt = 0; nt < 4; nt++) {
            const int col = n0 + wn + nt * 8 + qcol;
            const float b0 = __ldg(bias + col), b1 = __ldg(bias + col + 1);
            *(__half2*)(C + r0 + col) =
                __floats2half2_rn(ftanh(acc[mt][nt][0] + b0), ftanh(acc[mt][nt][1] + b1));
            *(__half2*)(C + r1 + col) =
                __floats2half2_rn(ftanh(acc[mt][nt][2] + b0), ftanh(acc[mt][nt][3] + b1));
        }
    }
}

// =====================================================================
// Kernel 3: neighborhood attention (k=7), vectorized half2/float2,
//   2 batches per 512-thread block
// =====================================================================
__global__ __launch_bounds__(512) void agent_attn_kernel(
    const __half2* __restrict__ E2, const __half2* __restrict__ V2,
    float2* __restrict__ out, __half2* __restrict__ outh)
{
    const int hb   = threadIdx.x >> 8;          // which batch half (0/1)
    const int t    = threadIdx.x & 255;
    const int b    = blockIdx.x * 2 + hb;
    __shared__ float2 sE[2][NNEIGH * HDIM2];    // 28KB
    __shared__ float2 q[2][HDIM2];              // 4KB
    __shared__ float  sc[2][8], p[2][8];

    const size_t base = (size_t)b * NNEIGH * HDIM2;
    for (int i = t; i < NNEIGH * HDIM2; i += 256)
        sE[hb][i] = __half22float2(E2[base + i]);
    __syncthreads();

    {
        float2 s = make_float2(0.f, 0.f);
        #pragma unroll
        for (int n = 0; n < NNEIGH; n++) {
            float2 e = sE[hb][n * HDIM2 + t];
            s.x += e.x; s.y += e.y;
        }
        q[hb][t] = make_float2(s.x * (1.f / 7.f), s.y * (1.f / 7.f));
    }
    __syncthreads();

    const int w = t >> 5, lane = t & 31;
    if (w < NNEIGH) {
        float s = 0.f;
        #pragma unroll
        for (int i = lane; i < HDIM2; i += 32) {
            float2 qq = q[hb][i], e = sE[hb][w * HDIM2 + i];
            s += qq.x * e.x + qq.y * e.y;
        }
        #pragma unroll
        for (int o = 16; o > 0; o >>= 1) s += __shfl_xor_sync(0xffffffffu, s, o);
        if (lane == 0) sc[hb][w] = s * 0.04419417382415922f;   // 1/sqrt(512)
    }
    __syncthreads();

    if (t == 0) {
        float m = sc[hb][0];
        #pragma unroll
        for (int n = 1; n < NNEIGH; n++) m = fmaxf(m, sc[hb][n]);
        float ssum = 0.f;
        #pragma unroll
        for (int n = 0; n < NNEIGH; n++) { p[hb][n] = __expf(sc[hb][n] - m); ssum += p[hb][n]; }
        float inv = 1.f / ssum;
        #pragma unroll
        for (int n = 0; n < NNEIGH; n++) p[hb][n] *= inv;
    }
    __syncthreads();

    {
        float2 s = make_float2(0.f, 0.f);
        #pragma unroll
        for (int n = 0; n < NNEIGH; n++) {
            float2 v = __half22float2(V2[base + n * HDIM2 + t]);
            s.x += p[hb][n] * v.x; s.y += p[hb][n] * v.y;
        }
        out [(size_t)b * HDIM2 + t] = s;
        outh[(size_t)b * HDIM2 + t] = __float22half2_rn(s);
    }
}

// =====================================================================
// Kernel 4: per-group multi-head attention (8 heads x 64, k=8), vectorized
// =====================================================================
__global__ __launch_bounds__(256) void multi_attn_kernel(
    const __half2* __restrict__ A2, const __half2* __restrict__ V2,
    float2* __restrict__ out)
{
    const int g = blockIdx.x;
    const int t = threadIdx.x;
    __shared__ float2 sA[8 * HDIM2];   // 16KB
    __shared__ float2 q[HDIM2];
    __shared__ float p[8][8];

    const size_t base = (size_t)g * 8 * HDIM2;
    for (int i = t; i < 8 * HDIM2; i += 256)
        sA[i] = __half22float2(A2[base + i]);
    __syncthreads();

    {
        float2 s = make_float2(0.f, 0.f);
        #pragma unroll
        for (int a = 0; a < 8; a++) {
            float2 e = sA[a * HDIM2 + t];
            s.x += e.x; s.y += e.y;
        }
        q[t] = make_float2(s.x * 0.125f, s.y * 0.125f);
    }
    __syncthreads();

    const int h = t >> 5, lane = t & 31;
    {
        const int a = lane & 7;
        float s = 0.f;
        #pragma unroll
        for (int i = 0; i < 32; i++) {
            const int idx = h * 32 + i;
            float2 qq = q[idx], e = sA[a * HDIM2 + idx];
            s += qq.x * e.x + qq.y * e.y;
        }
        s *= 0.125f;               // 1/sqrt(64)
        float m = s;
        #pragma unroll
        for (int o = 4; o > 0; o >>= 1) m = fmaxf(m, __shfl_xor_sync(0xffffffffu, m, o, 8));
        float e = __expf(s - m);
        float ssum = e;
        #pragma unroll
        for (int o = 4; o > 0; o >>= 1) ssum += __shfl_xor_sync(0xffffffffu, ssum, o, 8);
        if (lane < 8) p[h][lane] = e / ssum;
    }
    __syncthreads();

    {
        const int hh = t >> 5;
        float2 s = make_float2(0.f, 0.f);
        #pragma unroll
        for (int a = 0; a < 8; a++) {
            float2 v = __half22float2(V2[base + a * HDIM2 + t]);
            s.x += p[hh][a] * v.x; s.y += p[hh][a] * v.y;
        }
        #pragma unroll
        for (int rep = 0; rep < 8; rep++)
            out[((size_t)rep * NGROUPS + g) * HDIM2 + t] = s;
    }
}

// =====================================================================
// launch
// =====================================================================
extern "C" void kernel_launch(void* const* d_in, const int* in_sizes, int n_in,
                              void* d_out, int out_size)
{
    const float* self_obs = (const float*)d_in[0];
    const float* obs      = (const float*)d_in[1];
    const float* W_e1 = (const float*)d_in[2];  const float* b_e1 = (const float*)d_in[3];
    const float* W_e2 = (const float*)d_in[4];  const float* b_e2 = (const float*)d_in[5];
    const float* W_n1 = (const float*)d_in[6];  const float* b_n1 = (const float*)d_in[7];
    const float* W_n2 = (const float*)d_in[8];  const float* b_n2 = (const float*)d_in[9];
    const float* W_a1 = (const float*)d_in[10]; const float* b_a1 = (const float*)d_in[11];
    const float* W_a2 = (const float*)d_in[12]; const float* b_a2 = (const float*)d_in[13];

    float* out      = (float*)d_out;
    float* agentatt = out + OUT_HALF;

    __half *p_h1, *p_E, *p_V, *p_aa, *p_ah, *p_av, *p_Wt, *p_Wt1;
    cudaGetSymbolAddress((void**)&p_h1, g_h1h);
    cudaGetSymbolAddress((void**)&p_E,  g_Eh);
    cudaGetSymbolAddress((void**)&p_V,  g_Vh);
    cudaGetSymbolAddress((void**)&p_aa, g_aah);
    cudaGetSymbolAddress((void**)&p_ah, g_ahh);
    cudaGetSymbolAddress((void**)&p_av, g_avh);
    cudaGetSymbolAddress((void**)&p_Wt, g_Wt);
    cudaGetSymbolAddress((void**)&p_Wt1, g_Wt1);

    __half* Wt_e2 = p_Wt + 0 * (size_t)HDIM * HDIM;
    __half* Wt_n1 = p_Wt + 1 * (size_t)HDIM * HDIM;
    __half* Wt_n2 = p_Wt + 2 * (size_t)HDIM * HDIM;
    __half* Wt_a1 = p_Wt + 3 * (size_t)HDIM * HDIM;
    __half* Wt_a2 = p_Wt + 4 * (size_t)HDIM * HDIM;

    cudaFuncSetAttribute(gemm_hmma, cudaFuncAttributeMaxDynamicSharedMemorySize, GEMM_SMEM);

    // weight prep (1 launch: 5 transposes + W_e1 pad)
    prep_weights_kernel<<<dim3(16, 16, 6), dim3(32, 8)>>>(
        W_e2, W_n1, W_n2, W_a1, W_a2, p_Wt, W_e1, p_Wt1);

    // 1) h1 = tanh(gathered @ W_e1 + b_e1)   (HMMA, K=32 padded)
    embed1_hmma<<<dim3(4, MROWS / BM), 256>>>(self_obs, obs, p_Wt1, b_e1, p_h1);
    // 2-4) big GEMMs (grid: n fast for L2 A-reuse; 8 n-blocks of 64)
    gemm_hmma<<<dim3(8, MROWS / BM), 256, GEMM_SMEM>>>(p_h1, Wt_e2, b_e2, p_E);
    gemm_hmma<<<dim3(8, MROWS / BM), 256, GEMM_SMEM>>>(p_E,  Wt_n1, b_n1, p_h1);
    gemm_hmma<<<dim3(8, MROWS / BM), 256, GEMM_SMEM>>>(p_h1, Wt_n2, b_n2, p_V);
    // 5) neighborhood attention -> agent_attention (fp32 to d_out + fp16 copy)
    agent_attn_kernel<<<B_SZ / 2, 512>>>(
        (const __half2*)p_E, (const __half2*)p_V,
        (float2*)agentatt, (__half2*)p_aa);
    // 6-7) agent MLP
    gemm_hmma<<<dim3(8, B_SZ / BM), 256, GEMM_SMEM>>>(p_aa, Wt_a1, b_a1, p_ah);
    gemm_hmma<<<dim3(8, B_SZ / BM), 256, GEMM_SMEM>>>(p_ah, Wt_a2, b_a2, p_av);
    // 8) multi-head attention -> first half of d_out (x8 tiled)
    multi_attn_kernel<<<NGROUPS, 256>>>(
        (const __half2*)p_aa, (const __half2*)p_av, (float2*)out);
}

// round 10
// speedup vs baseline: 1.0495x; 1.0495x over previous
#include <cuda_runtime.h>
#include <cuda_fp16.h>
#include <cstdint>

// ---------------- problem constants ----------------
#define B_SZ     16384
#define NNEIGH   7
#define HDIM     512
#define HDIM2    256                   // HDIM in half2/float2 units
#define MROWS    (B_SZ * NNEIGH)      // 114688
#define SELF_W   18
#define NEIGH_W  6
#define OBS_W    (SELF_W + NEIGH_W * NNEIGH)  // 60
#define NGROUPS  (B_SZ / 8)           // 2048
#define OUT_HALF ((size_t)B_SZ * HDIM)

// GEMM tiling (R8 optimum: 128x128, warp 64x32, 2 CTAs/SM, 3 stages)
#define BM   128
#define BN   128
#define BKH  64                        // halves per K chunk (128 bytes/row)
#define NCHUNK (HDIM / BKH)            // 8
#define TILE_BYTES (BM * BKH * 2)      // 16384
#define STAGE_BYTES (2 * TILE_BYTES)   // A+B per stage = 32768
#define STAGES 3
#define GEMM_SMEM (STAGES * STAGE_BYTES)  // 96KB

// ---------------- scratch (__device__ globals; no allocs allowed) ---------
__device__ __half g_h1h[(size_t)MROWS * HDIM];
__device__ __half g_Eh [(size_t)MROWS * HDIM];
__device__ __half g_Vh [(size_t)MROWS * HDIM];
__device__ __half g_aah[(size_t)B_SZ * HDIM];
__device__ __half g_ahh[(size_t)B_SZ * HDIM];
__device__ __half g_avh[(size_t)B_SZ * HDIM];
__device__ __half g_Wt [5 * (size_t)HDIM * HDIM];
__device__ __half g_Wt1[(size_t)HDIM * 32];     // W_e1^T padded to K=32

// ---------------- small helpers ----------------
__device__ __forceinline__ uint32_t smem_u32(const void* p) {
    uint32_t a;
    asm("{ .reg .u64 t; cvta.to.shared.u64 t, %1; cvt.u32.u64 %0, t; }" : "=r"(a) : "l"(p));
    return a;
}
__device__ __forceinline__ void cp16(uint32_t s, const void* g) {
    asm volatile("cp.async.cg.shared.global [%0], [%1], 16;" :: "r"(s), "l"(g));
}
#define CP_COMMIT()  asm volatile("cp.async.commit_group;" ::: "memory")
#define CP_WAIT(n)   asm volatile("cp.async.wait_group %0;" :: "n"(n) : "memory")

__device__ __forceinline__ void ldmx4(uint32_t addr, uint32_t* r) {
    asm volatile("ldmatrix.sync.aligned.m8n8.x4.shared.b16 {%0,%1,%2,%3}, [%4];"
        : "=r"(r[0]), "=r"(r[1]), "=r"(r[2]), "=r"(r[3]) : "r"(addr));
}
__device__ __forceinline__ void mma16816(float* c, const uint32_t* a, uint32_t b0, uint32_t b1) {
    asm volatile("mma.sync.aligned.m16n8k16.row.col.f32.f16.f16.f32 "
        "{%0,%1,%2,%3},{%4,%5,%6,%7},{%8,%9},{%0,%1,%2,%3};"
        : "+f"(c[0]), "+f"(c[1]), "+f"(c[2]), "+f"(c[3])
        : "r"(a[0]), "r"(a[1]), "r"(a[2]), "r"(a[3]), "r"(b0), "r"(b1));
}
__device__ __forceinline__ uint32_t sw128(uint32_t off) {   // SW128 swizzle
    return off ^ ((off >> 3) & 0x70);
}
// single-MUFU tanh (sm_75+); max rel err ~2^-11 == fp16 quantization scale
__device__ __forceinline__ float ftanh(float x) {
    float r;
    asm("tanh.approx.f32 %0, %1;" : "=f"(r) : "f"(x));
    return r;
}

// =====================================================================
// Weight prep: 5 transposes (z=0..4) + W_e1 pad/transpose (z=5)
// =====================================================================
__global__ __launch_bounds__(256) void prep_weights_kernel(
    const float* __restrict__ W0, const float* __restrict__ W1,
    const float* __restrict__ W2, const float* __restrict__ W3,
    const float* __restrict__ W4, __half* __restrict__ WtBase,
    const float* __restrict__ We1, __half* __restrict__ Wt1)
{
    __shared__ float t[32][33];
    if (blockIdx.z == 5) {
        const int ftid = threadIdx.y * 32 + threadIdx.x;
        const int idx = (blockIdx.y * 16 + blockIdx.x) * 256 + ftid;
        if (idx < HDIM * 32) {
            const int n = idx >> 5, k = idx & 31;
            Wt1[idx] = (k < 24) ? __float2half(We1[(size_t)k * HDIM + n]) : __half(0.f);
        }
        return;
    }
    const float* W;
    switch (blockIdx.z) {
        case 0: W = W0; break;
        case 1: W = W1; break;
        case 2: W = W2; break;
        case 3: W = W3; break;
        default: W = W4; break;
    }
    __half* Wt = WtBase + (size_t)blockIdx.z * HDIM * HDIM;
    const int bx = blockIdx.x * 32, by = blockIdx.y * 32;
    #pragma unroll
    for (int i = threadIdx.y; i < 32; i += 8)
        t[i][threadIdx.x] = W[(size_t)(by + i) * HDIM + bx + threadIdx.x];
    __syncthreads();
    #pragma unroll
    for (int i = threadIdx.y; i < 32; i += 8)
        Wt[(size_t)(bx + i) * HDIM + by + threadIdx.x] = __float2half(t[threadIdx.x][i]);
}

// =====================================================================
// Kernel 1: fused gather + HMMA GEMM (K=24 pad 32) + bias + tanh -> fp16
// =====================================================================
__global__ __launch_bounds__(256) void embed1_hmma(
    const float* __restrict__ self_obs, const float* __restrict__ obs,
    const __half* __restrict__ Wt1, const float* __restrict__ bias,
    __half* __restrict__ C)
{
    __shared__ __align__(128) unsigned char sm[2 * 16384];  // A, B (128 rows x 128B)
    const uint32_t sbase = smem_u32(sm);
    const int tid  = threadIdx.x;
    const int wid  = tid >> 5, lane = tid & 31;
    const int n0   = blockIdx.x * BN;
    const int m0   = blockIdx.y * BM;
    const int wm   = (wid >> 2) * 64;
    const int wn   = (wid & 3) * 32;

    // ---- fill tiles: each thread 1 half-row (32B = 16 halves) ----
    const int row = tid >> 1, seg = tid & 1;
    {
        const int j = m0 + row;
        const int sb = (j % B_SZ) * SELF_W;
        const int ob = (j / NNEIGH) * OBS_W + SELF_W + (j % NNEIGH) * NEIGH_W;
        __half vals[16];
        #pragma unroll
        for (int c = 0; c < 16; c++) {
            const int k = seg * 16 + c;
            float v = 0.f;
            if (k < SELF_W)      v = __ldg(self_obs + sb + k);
            else if (k < 24)     v = __ldg(obs + ob + (k - SELF_W));
            vals[c] = __float2half(v);
        }
        const uint32_t base = (uint32_t)row * 128 + (uint32_t)seg * 32;
        *(uint4*)(sm + sw128(base))      = ((const uint4*)vals)[0];
        *(uint4*)(sm + sw128(base + 16)) = ((const uint4*)vals)[1];
        const __half* bsrc = Wt1 + (size_t)(n0 + row) * 32 + seg * 16;
        *(uint4*)(sm + 16384 + sw128(base))      = *(const uint4*)bsrc;
        *(uint4*)(sm + 16384 + sw128(base + 16)) = *(const uint4*)(bsrc + 8);
    }
    __syncthreads();

    const int arow = wm + ((lane >> 3) & 1) * 8 + (lane & 7);
    const uint32_t acolbase = ((lane >> 4) & 1) * 16;
    const int brow = wn + ((lane >> 4) & 1) * 8 + (lane & 7);
    const uint32_t bcolbase = ((lane >> 3) & 1) * 16;

    float acc[4][4][4];
    #pragma unroll
    for (int mt = 0; mt < 4; mt++)
        #pragma unroll
        for (int nt = 0; nt < 4; nt++)
            #pragma unroll
            for (int e = 0; e < 4; e++) acc[mt][nt][e] = 0.f;

    const uint32_t sA = sbase, sB = sbase + 16384;
    #pragma unroll
    for (int ks = 0; ks < 2; ks++) {
        uint32_t bf[2][4];
        #pragma unroll
        for (int g = 0; g < 2; g++) {
            int r = brow + g * 16;
            uint32_t col = (bcolbase + ks * 32) ^ (((uint32_t)(r & 7)) << 4);
            ldmx4(sB + (uint32_t)r * 128 + col, bf[g]);
        }
        uint32_t af[4];
        #pragma unroll
        for (int mt = 0; mt < 4; mt++) {
            int r = arow + mt * 16;
            uint32_t col = (acolbase + ks * 32) ^ (((uint32_t)(r & 7)) << 4);
            ldmx4(sA + (uint32_t)r * 128 + col, af);
            #pragma unroll
            for (int g = 0; g < 2; g++) {
                mma16816(acc[mt][2 * g],     af, bf[g][0], bf[g][1]);
                mma16816(acc[mt][2 * g + 1], af, bf[g][2], bf[g][3]);
            }
        }
    }

    const int qrow = lane >> 2;
    const int qcol = (lane & 3) * 2;
    #pragma unroll
    for (int mt = 0; mt < 4; mt++) {
        const size_t r0 = (size_t)(m0 + wm + mt * 16 + qrow) * HDIM;
        const size_t r1 = r0 + 8 * HDIM;
        #pragma unroll
        for (int nt = 0; nt < 4; nt++) {
            const int col = n0 + wn + nt * 8 + qcol;
            const float b0 = __ldg(bias + col), b1 = __ldg(bias + col + 1);
            *(__half2*)(C + r0 + col) =
                __floats2half2_rn(ftanh(acc[mt][nt][0] + b0), ftanh(acc[mt][nt][1] + b1));
            *(__half2*)(C + r1 + col) =
                __floats2half2_rn(ftanh(acc[mt][nt][2] + b0), ftanh(acc[mt][nt][3] + b1));
        }
    }
}

// =====================================================================
// Kernel 2: HMMA fp16 GEMM (R8 optimum config), fast tanh epilogue
//   C = (half) tanh(A @ Wt^T + bias); grid (4, m_blocks)
// =====================================================================
__global__ __launch_bounds__(256, 2) void gemm_hmma(
    const __half* __restrict__ A, const __half* __restrict__ Wt,
    const float* __restrict__ bias, __half* __restrict__ C)
{
    extern __shared__ __align__(16) unsigned char smem[];
    const uint32_t sbase = smem_u32(smem);
    const int tid  = threadIdx.x;
    const int wid  = tid >> 5, lane = tid & 31;
    const int n0   = blockIdx.x * BN;
    const int m0   = blockIdx.y * BM;
    const int wm   = (wid >> 2) * 64;
    const int wn   = (wid & 3) * 32;

    // ---- cp.async loader mapping ----
    const int lrow = tid >> 3, lseg = tid & 7;
    uint32_t swoff[4];
    #pragma unroll
    for (int i = 0; i < 4; i++)
        swoff[i] = sw128((uint32_t)(lrow + i * 32) * 128 + (uint32_t)lseg * 16);
    const __half* gA = A  + (size_t)(m0 + lrow) * HDIM + lseg * 8;
    const __half* gB = Wt + (size_t)(n0 + lrow) * HDIM + lseg * 8;

    // ---- hoisted ldmatrix address components ----
    const int arow = wm + ((lane >> 3) & 1) * 8 + (lane & 7);
    const uint32_t mA = ((uint32_t)(arow & 7)) << 4;
    const uint32_t acb = (((lane >> 4) & 1) * 16) ^ (mA & 16u);
    const int brow = wn + ((lane >> 4) & 1) * 8 + (lane & 7);
    const uint32_t mB = ((uint32_t)(brow & 7)) << 4;
    const uint32_t bcb = (((lane >> 3) & 1) * 16) ^ (mB & 16u);
    uint32_t aoff[4], boff[2], ksoA[4], ksoB[4];
    #pragma unroll
    for (int mt = 0; mt < 4; mt++) aoff[mt] = (uint32_t)(arow + mt * 16) * 128 + acb;
    #pragma unroll
    for (int g = 0; g < 2; g++)    boff[g]  = (uint32_t)(brow + g * 16) * 128 + bcb + TILE_BYTES;
    #pragma unroll
    for (int ks = 0; ks < 4; ks++) {
        ksoA[ks] = ((uint32_t)(ks * 32)) ^ (mA & 0x60u);
        ksoB[ks] = ((uint32_t)(ks * 32)) ^ (mB & 0x60u);
    }

    float acc[4][4][4];
    #pragma unroll
    for (int mt = 0; mt < 4; mt++)
        #pragma unroll
        for (int nt = 0; nt < 4; nt++)
            #pragma unroll
            for (int e = 0; e < 4; e++) acc[mt][nt][e] = 0.f;

    // ---- prologue: stages 0,1 ----
    #pragma unroll
    for (int s = 0; s < 2; s++) {
        const uint32_t dst = sbase + s * STAGE_BYTES;
        #pragma unroll
        for (int i = 0; i < 4; i++) {
            cp16(dst + swoff[i],              gA + s * BKH + (size_t)i * 32 * HDIM);
            cp16(dst + TILE_BYTES + swoff[i], gB + s * BKH + (size_t)i * 32 * HDIM);
        }
        CP_COMMIT();
    }

    uint32_t cstage = 0, lstage = 2;
    #pragma unroll 1
    for (int c = 0; c < NCHUNK; c++) {
        CP_WAIT(1);
        __syncthreads();
        if (c + 2 < NCHUNK) {
            const uint32_t dst = sbase + lstage * STAGE_BYTES;
            #pragma unroll
            for (int i = 0; i < 4; i++) {
                cp16(dst + swoff[i],              gA + (c + 2) * BKH + (size_t)i * 32 * HDIM);
                cp16(dst + TILE_BYTES + swoff[i], gB + (c + 2) * BKH + (size_t)i * 32 * HDIM);
            }
            if (++lstage == STAGES) lstage = 0;
            CP_COMMIT();
        } else {
            CP_COMMIT();
        }

        const uint32_t sS = sbase + cstage * STAGE_BYTES;
        #pragma unroll
        for (int ks = 0; ks < 4; ks++) {
            uint32_t bf[2][4];
            ldmx4(sS + boff[0] + ksoB[ks], bf[0]);
            ldmx4(sS + boff[1] + ksoB[ks], bf[1]);
            uint32_t af[4];
            #pragma unroll
            for (int mt = 0; mt < 4; mt++) {
                ldmx4(sS + aoff[mt] + ksoA[ks], af);
                #pragma unroll
                for (int g = 0; g < 2; g++) {
                    mma16816(acc[mt][2 * g],     af, bf[g][0], bf[g][1]);
                    mma16816(acc[mt][2 * g + 1], af, bf[g][2], bf[g][3]);
                }
            }
        }
        if (++cstage == STAGES) cstage = 0;
    }

    // ---- epilogue: bias + tanh.approx -> fp16 ----
    const int qrow = lane >> 2;
    const int qcol = (lane & 3) * 2;
    #pragma unroll
    for (int mt = 0; mt < 4; mt++) {
        const size_t r0 = (size_t)(m0 + wm + mt * 16 + qrow) * HDIM;
        const size_t r1 = r0 + 8 * HDIM;
        #pragma unroll
        for (int nt = 0; nt < 4; nt++) {
            const int col = n0 + wn + nt * 8 + qcol;
            const float b0 = __ldg(bias + col), b1 = __ldg(bias + col + 1);
            *(__half2*)(C + r0 + col) =
                __floats2half2_rn(ftanh(acc[mt][nt][0] + b0), ftanh(acc[mt][nt][1] + b1));
            *(__half2*)(C + r1 + col) =
                __floats2half2_rn(ftanh(acc[mt][nt][2] + b0), ftanh(acc[mt][nt][3] + b1));
        }
    }
}

// =====================================================================
// Kernel 3: neighborhood attention (k=7), vectorized half2/float2,
//   2 batches per 512-thread block
// =====================================================================
__global__ __launch_bounds__(512) void agent_attn_kernel(
    const __half2* __restrict__ E2, const __half2* __restrict__ V2,
    float2* __restrict__ out, __half2* __restrict__ outh)
{
    const int hb   = threadIdx.x >> 8;          // which batch half (0/1)
    const int t    = threadIdx.x & 255;
    const int b    = blockIdx.x * 2 + hb;
    __shared__ float2 sE[2][NNEIGH * HDIM2];    // 28KB
    __shared__ float2 q[2][HDIM2];              // 4KB
    __shared__ float  sc[2][8], p[2][8];

    const size_t base = (size_t)b * NNEIGH * HDIM2;
    for (int i = t; i < NNEIGH * HDIM2; i += 256)
        sE[hb][i] = __half22float2(E2[base + i]);
    __syncthreads();

    {
        float2 s = make_float2(0.f, 0.f);
        #pragma unroll
        for (int n = 0; n < NNEIGH; n++) {
            float2 e = sE[hb][n * HDIM2 + t];
            s.x += e.x; s.y += e.y;
        }
        q[hb][t] = make_float2(s.x * (1.f / 7.f), s.y * (1.f / 7.f));
    }
    __syncthreads();

    const int w = t >> 5, lane = t & 31;
    if (w < NNEIGH) {
        float s = 0.f;
        #pragma unroll
        for (int i = lane; i < HDIM2; i += 32) {
            float2 qq = q[hb][i], e = sE[hb][w * HDIM2 + i];
            s += qq.x * e.x + qq.y * e.y;
        }
        #pragma unroll
        for (int o = 16; o > 0; o >>= 1) s += __shfl_xor_sync(0xffffffffu, s, o);
        if (lane == 0) sc[hb][w] = s * 0.04419417382415922f;   // 1/sqrt(512)
    }
    __syncthreads();

    if (t == 0) {
        float m = sc[hb][0];
        #pragma unroll
        for (int n = 1; n < NNEIGH; n++) m = fmaxf(m, sc[hb][n]);
        float ssum = 0.f;
        #pragma unroll
        for (int n = 0; n < NNEIGH; n++) { p[hb][n] = __expf(sc[hb][n] - m); ssum += p[hb][n]; }
        float inv = 1.f / ssum;
        #pragma unroll
        for (int n = 0; n < NNEIGH; n++) p[hb][n] *= inv;
    }
    __syncthreads();

    {
        float2 s = make_float2(0.f, 0.f);
        #pragma unroll
        for (int n = 0; n < NNEIGH; n++) {
            float2 v = __half22float2(V2[base + n * HDIM2 + t]);
            s.x += p[hb][n] * v.x; s.y += p[hb][n] * v.y;
        }
        out [(size_t)b * HDIM2 + t] = s;
        outh[(size_t)b * HDIM2 + t] = __float22half2_rn(s);
    }
}

// =====================================================================
// Kernel 4: per-group multi-head attention (8 heads x 64, k=8), vectorized
// =====================================================================
__global__ __launch_bounds__(256) void multi_attn_kernel(
    const __half2* __restrict__ A2, const __half2* __restrict__ V2,
    float2* __restrict__ out)
{
    const int g = blockIdx.x;
    const int t = threadIdx.x;
    __shared__ float2 sA[8 * HDIM2];   // 16KB
    __shared__ float2 q[HDIM2];
    __shared__ float p[8][8];

    const size_t base = (size_t)g * 8 * HDIM2;
    for (int i = t; i < 8 * HDIM2; i += 256)
        sA[i] = __half22float2(A2[base + i]);
    __syncthreads();

    {
        float2 s = make_float2(0.f, 0.f);
        #pragma unroll
        for (int a = 0; a < 8; a++) {
            float2 e = sA[a * HDIM2 + t];
            s.x += e.x; s.y += e.y;
        }
        q[t] = make_float2(s.x * 0.125f, s.y * 0.125f);
    }
    __syncthreads();

    const int h = t >> 5, lane = t & 31;
    {
        const int a = lane & 7;
        float s = 0.f;
        #pragma unroll
        for (int i = 0; i < 32; i++) {
            const int idx = h * 32 + i;
            float2 qq = q[idx], e = sA[a * HDIM2 + idx];
            s += qq.x * e.x + qq.y * e.y;
        }
        s *= 0.125f;               // 1/sqrt(64)
        float m = s;
        #pragma unroll
        for (int o = 4; o > 0; o >>= 1) m = fmaxf(m, __shfl_xor_sync(0xffffffffu, m, o, 8));
        float e = __expf(s - m);
        float ssum = e;
        #pragma unroll
        for (int o = 4; o > 0; o >>= 1) ssum += __shfl_xor_sync(0xffffffffu, ssum, o, 8);
        if (lane < 8) p[h][lane] = e / ssum;
    }
    __syncthreads();

    {
        const int hh = t >> 5;
        float2 s = make_float2(0.f, 0.f);
        #pragma unroll
        for (int a = 0; a < 8; a++) {
            float2 v = __half22float2(V2[base + a * HDIM2 + t]);
            s.x += p[hh][a] * v.x; s.y += p[hh][a] * v.y;
        }
        #pragma unroll
        for (int rep = 0; rep < 8; rep++)
            out[((size_t)rep * NGROUPS + g) * HDIM2 + t] = s;
    }
}

// =====================================================================
// launch
// =====================================================================
extern "C" void kernel_launch(void* const* d_in, const int* in_sizes, int n_in,
                              void* d_out, int out_size)
{
    const float* self_obs = (const float*)d_in[0];
    const float* obs      = (const float*)d_in[1];
    const float* W_e1 = (const float*)d_in[2];  const float* b_e1 = (const float*)d_in[3];
    const float* W_e2 = (const float*)d_in[4];  const float* b_e2 = (const float*)d_in[5];
    const float* W_n1 = (const float*)d_in[6];  const float* b_n1 = (const float*)d_in[7];
    const float* W_n2 = (const float*)d_in[8];  const float* b_n2 = (const float*)d_in[9];
    const float* W_a1 = (const float*)d_in[10]; const float* b_a1 = (const float*)d_in[11];
    const float* W_a2 = (const float*)d_in[12]; const float* b_a2 = (const float*)d_in[13];

    float* out      = (float*)d_out;
    float* agentatt = out + OUT_HALF;

    __half *p_h1, *p_E, *p_V, *p_aa, *p_ah, *p_av, *p_Wt, *p_Wt1;
    cudaGetSymbolAddress((void**)&p_h1, g_h1h);
    cudaGetSymbolAddress((void**)&p_E,  g_Eh);
    cudaGetSymbolAddress((void**)&p_V,  g_Vh);
    cudaGetSymbolAddress((void**)&p_aa, g_aah);
    cudaGetSymbolAddress((void**)&p_ah, g_ahh);
    cudaGetSymbolAddress((void**)&p_av, g_avh);
    cudaGetSymbolAddress((void**)&p_Wt, g_Wt);
    cudaGetSymbolAddress((void**)&p_Wt1, g_Wt1);

    __half* Wt_e2 = p_Wt + 0 * (size_t)HDIM * HDIM;
    __half* Wt_n1 = p_Wt + 1 * (size_t)HDIM * HDIM;
    __half* Wt_n2 = p_Wt + 2 * (size_t)HDIM * HDIM;
    __half* Wt_a1 = p_Wt + 3 * (size_t)HDIM * HDIM;
    __half* Wt_a2 = p_Wt + 4 * (size_t)HDIM * HDIM;

    cudaFuncSetAttribute(gemm_hmma, cudaFuncAttributeMaxDynamicSharedMemorySize, GEMM_SMEM);

    // weight prep (1 launch: 5 transposes + W_e1 pad)
    prep_weights_kernel<<<dim3(16, 16, 6), dim3(32, 8)>>>(
        W_e2, W_n1, W_n2, W_a1, W_a2, p_Wt, W_e1, p_Wt1);

    // 1) h1 = tanh(gathered @ W_e1 + b_e1)   (HMMA, K=32 padded)
    embed1_hmma<<<dim3(4, MROWS / BM), 256>>>(self_obs, obs, p_Wt1, b_e1, p_h1);
    // 2-4) big GEMMs (grid: n fast for L2 A-reuse)
    gemm_hmma<<<dim3(4, MROWS / BM), 256, GEMM_SMEM>>>(p_h1, Wt_e2, b_e2, p_E);
    gemm_hmma<<<dim3(4, MROWS / BM), 256, GEMM_SMEM>>>(p_E,  Wt_n1, b_n1, p_h1);
    gemm_hmma<<<dim3(4, MROWS / BM), 256, GEMM_SMEM>>>(p_h1, Wt_n2, b_n2, p_V);
    // 5) neighborhood attention -> agent_attention (fp32 to d_out + fp16 copy)
    agent_attn_kernel<<<B_SZ / 2, 512>>>(
        (const __half2*)p_E, (const __half2*)p_V,
        (float2*)agentatt, (__half2*)p_aa);
    // 6-7) agent MLP
    gemm_hmma<<<dim3(4, B_SZ / BM), 256, GEMM_SMEM>>>(p_aa, Wt_a1, b_a1, p_ah);
    gemm_hmma<<<dim3(4, B_SZ / BM), 256, GEMM_SMEM>>>(p_ah, Wt_a2, b_a2, p_av);
    // 8) multi-head attention -> first half of d_out (x8 tiled)
    multi_attn_kernel<<<NGROUPS, 256>>>(
        (const __half2*)p_aa, (const __half2*)p_av, (float2*)out);
}

// round 12
// speedup vs baseline: 1.0690x; 1.0186x over previous
#include <cuda_runtime.h>
#include <cuda_fp16.h>
#include <cstdint>

// ---------------- problem constants ----------------
#define B_SZ     16384
#define NNEIGH   7
#define HDIM     512
#define HDIM2    256                   // HDIM in half2/float2 units
#define MROWS    (B_SZ * NNEIGH)      // 114688
#define SELF_W   18
#define NEIGH_W  6
#define OBS_W    (SELF_W + NEIGH_W * NNEIGH)  // 60
#define NGROUPS  (B_SZ / 8)           // 2048
#define OUT_HALF ((size_t)B_SZ * HDIM)

// GEMM tiling (R8 optimum: 128x128, warp 64x32, 2 CTAs/SM, 3 stages)
#define BM   128
#define BN   128
#define BKH  64                        // halves per K chunk (128 bytes/row)
#define NCHUNK (HDIM / BKH)            // 8
#define TILE_BYTES (BM * BKH * 2)      // 16384
#define STAGE_BYTES (2 * TILE_BYTES)   // A+B per stage = 32768
#define STAGES 3
#define GEMM_SMEM (STAGES * STAGE_BYTES)  // 96KB

// ---------------- scratch (__device__ globals; no allocs allowed) ---------
__device__ __half g_h1h[(size_t)MROWS * HDIM];
__device__ __half g_Eh [(size_t)MROWS * HDIM];
__device__ __half g_Vh [(size_t)MROWS * HDIM];
__device__ __half g_aah[(size_t)B_SZ * HDIM];
__device__ __half g_ahh[(size_t)B_SZ * HDIM];
__device__ __half g_avh[(size_t)B_SZ * HDIM];
__device__ __half g_Wt [5 * (size_t)HDIM * HDIM];
__device__ __half g_Wt1[(size_t)HDIM * 32];     // W_e1^T padded to K=32

// ---------------- small helpers ----------------
__device__ __forceinline__ uint32_t smem_u32(const void* p) {
    uint32_t a;
    asm("{ .reg .u64 t; cvta.to.shared.u64 t, %1; cvt.u32.u64 %0, t; }" : "=r"(a) : "l"(p));
    return a;
}
__device__ __forceinline__ void cp16(uint32_t s, const void* g) {
    asm volatile("cp.async.cg.shared.global [%0], [%1], 16;" :: "r"(s), "l"(g));
}
#define CP_COMMIT()  asm volatile("cp.async.commit_group;" ::: "memory")
#define CP_WAIT(n)   asm volatile("cp.async.wait_group %0;" :: "n"(n) : "memory")

__device__ __forceinline__ void ldmx4(uint32_t addr, uint32_t* r) {
    asm volatile("ldmatrix.sync.aligned.m8n8.x4.shared.b16 {%0,%1,%2,%3}, [%4];"
        : "=r"(r[0]), "=r"(r[1]), "=r"(r[2]), "=r"(r[3]) : "r"(addr));
}
__device__ __forceinline__ void mma16816(float* c, const uint32_t* a, uint32_t b0, uint32_t b1) {
    asm volatile("mma.sync.aligned.m16n8k16.row.col.f32.f16.f16.f32 "
        "{%0,%1,%2,%3},{%4,%5,%6,%7},{%8,%9},{%0,%1,%2,%3};"
        : "+f"(c[0]), "+f"(c[1]), "+f"(c[2]), "+f"(c[3])
        : "r"(a[0]), "r"(a[1]), "r"(a[2]), "r"(a[3]), "r"(b0), "r"(b1));
}
__device__ __forceinline__ uint32_t sw128(uint32_t off) {   // SW128 swizzle
    return off ^ ((off >> 3) & 0x70);
}
// single-MUFU tanh (sm_75+); max rel err ~2^-11 == fp16 quantization scale
__device__ __forceinline__ float ftanh(float x) {
    float r;
    asm("tanh.approx.f32 %0, %1;" : "=f"(r) : "f"(x));
    return r;
}

// =====================================================================
// Weight prep: 5 transposes (z=0..4) + W_e1 pad/transpose (z=5)
// =====================================================================
__global__ __launch_bounds__(256) void prep_weights_kernel(
    const float* __restrict__ W0, const float* __restrict__ W1,
    const float* __restrict__ W2, const float* __restrict__ W3,
    const float* __restrict__ W4, __half* __restrict__ WtBase,
    const float* __restrict__ We1, __half* __restrict__ Wt1)
{
    __shared__ float t[32][33];
    if (blockIdx.z == 5) {
        const int ftid = threadIdx.y * 32 + threadIdx.x;
        const int idx = (blockIdx.y * 16 + blockIdx.x) * 256 + ftid;
        if (idx < HDIM * 32) {
            const int n = idx >> 5, k = idx & 31;
            Wt1[idx] = (k < 24) ? __float2half(We1[(size_t)k * HDIM + n]) : __half(0.f);
        }
        return;
    }
    const float* W;
    switch (blockIdx.z) {
        case 0: W = W0; break;
        case 1: W = W1; break;
        case 2: W = W2; break;
        case 3: W = W3; break;
        default: W = W4; break;
    }
    __half* Wt = WtBase + (size_t)blockIdx.z * HDIM * HDIM;
    const int bx = blockIdx.x * 32, by = blockIdx.y * 32;
    #pragma unroll
    for (int i = threadIdx.y; i < 32; i += 8)
        t[i][threadIdx.x] = W[(size_t)(by + i) * HDIM + bx + threadIdx.x];
    __syncthreads();
    #pragma unroll
    for (int i = threadIdx.y; i < 32; i += 8)
        Wt[(size_t)(bx + i) * HDIM + by + threadIdx.x] = __float2half(t[threadIdx.x][i]);
}

// =====================================================================
// Kernel 1: fused gather + HMMA GEMM (K=24 pad 32) + bias + tanh -> fp16
// =====================================================================
__global__ __launch_bounds__(256) void embed1_hmma(
    const float* __restrict__ self_obs, const float* __restrict__ obs,
    const __half* __restrict__ Wt1, const float* __restrict__ bias,
    __half* __restrict__ C)
{
    __shared__ __align__(128) unsigned char sm[2 * 16384];  // A, B (128 rows x 128B)
    const uint32_t sbase = smem_u32(sm);
    const int tid  = threadIdx.x;
    const int wid  = tid >> 5, lane = tid & 31;
    const int n0   = blockIdx.x * BN;
    const int m0   = blockIdx.y * BM;
    const int wm   = (wid >> 2) * 64;
    const int wn   = (wid & 3) * 32;

    // ---- fill tiles: each thread 1 half-row (32B = 16 halves) ----
    const int row = tid >> 1, seg = tid & 1;
    {
        const int j = m0 + row;
        const int sb = (j % B_SZ) * SELF_W;
        const int ob = (j / NNEIGH) * OBS_W + SELF_W + (j % NNEIGH) * NEIGH_W;
        __half vals[16];
        #pragma unroll
        for (int c = 0; c < 16; c++) {
            const int k = seg * 16 + c;
            float v = 0.f;
            if (k < SELF_W)      v = __ldg(self_obs + sb + k);
            else if (k < 24)     v = __ldg(obs + ob + (k - SELF_W));
            vals[c] = __float2half(v);
        }
        const uint32_t base = (uint32_t)row * 128 + (uint32_t)seg * 32;
        *(uint4*)(sm + sw128(base))      = ((const uint4*)vals)[0];
        *(uint4*)(sm + sw128(base + 16)) = ((const uint4*)vals)[1];
        const __half* bsrc = Wt1 + (size_t)(n0 + row) * 32 + seg * 16;
        *(uint4*)(sm + 16384 + sw128(base))      = *(const uint4*)bsrc;
        *(uint4*)(sm + 16384 + sw128(base + 16)) = *(const uint4*)(bsrc + 8);
    }
    __syncthreads();

    const int arow = wm + ((lane >> 3) & 1) * 8 + (lane & 7);
    const uint32_t acolbase = ((lane >> 4) & 1) * 16;
    const int brow = wn + ((lane >> 4) & 1) * 8 + (lane & 7);
    const uint32_t bcolbase = ((lane >> 3) & 1) * 16;

    float acc[4][4][4];
    #pragma unroll
    for (int mt = 0; mt < 4; mt++)
        #pragma unroll
        for (int nt = 0; nt < 4; nt++)
            #pragma unroll
            for (int e = 0; e < 4; e++) acc[mt][nt][e] = 0.f;

    const uint32_t sA = sbase, sB = sbase + 16384;
    #pragma unroll
    for (int ks = 0; ks < 2; ks++) {
        uint32_t bf[2][4];
        #pragma unroll
        for (int g = 0; g < 2; g++) {
            int r = brow + g * 16;
            uint32_t col = (bcolbase + ks * 32) ^ (((uint32_t)(r & 7)) << 4);
            ldmx4(sB + (uint32_t)r * 128 + col, bf[g]);
        }
        uint32_t af[4];
        #pragma unroll
        for (int mt = 0; mt < 4; mt++) {
            int r = arow + mt * 16;
            uint32_t col = (acolbase + ks * 32) ^ (((uint32_t)(r & 7)) << 4);
            ldmx4(sA + (uint32_t)r * 128 + col, af);
            #pragma unroll
            for (int g = 0; g < 2; g++) {
                mma16816(acc[mt][2 * g],     af, bf[g][0], bf[g][1]);
                mma16816(acc[mt][2 * g + 1], af, bf[g][2], bf[g][3]);
            }
        }
    }

    const int qrow = lane >> 2;
    const int qcol = (lane & 3) * 2;
    #pragma unroll
    for (int mt = 0; mt < 4; mt++) {
        const size_t r0 = (size_t)(m0 + wm + mt * 16 + qrow) * HDIM;
        const size_t r1 = r0 + 8 * HDIM;
        #pragma unroll
        for (int nt = 0; nt < 4; nt++) {
            const int col = n0 + wn + nt * 8 + qcol;
            const float b0 = __ldg(bias + col), b1 = __ldg(bias + col + 1);
            *(__half2*)(C + r0 + col) =
                __floats2half2_rn(ftanh(acc[mt][nt][0] + b0), ftanh(acc[mt][nt][1] + b1));
            *(__half2*)(C + r1 + col) =
                __floats2half2_rn(ftanh(acc[mt][nt][2] + b0), ftanh(acc[mt][nt][3] + b1));
        }
    }
}

// =====================================================================
// Kernel 2: HMMA fp16 GEMM (R8 optimum config), fast tanh epilogue
//   C = (half) tanh(A @ Wt^T + bias); grid (4, m_blocks)
// =====================================================================
__global__ __launch_bounds__(256, 2) void gemm_hmma(
    const __half* __restrict__ A, const __half* __restrict__ Wt,
    const float* __restrict__ bias, __half* __restrict__ C)
{
    extern __shared__ __align__(16) unsigned char smem[];
    const uint32_t sbase = smem_u32(smem);
    const int tid  = threadIdx.x;
    const int wid  = tid >> 5, lane = tid & 31;
    const int n0   = blockIdx.x * BN;
    const int m0   = blockIdx.y * BM;
    const int wm   = (wid >> 2) * 64;
    const int wn   = (wid & 3) * 32;

    // ---- cp.async loader mapping ----
    const int lrow = tid >> 3, lseg = tid & 7;
    uint32_t swoff[4];
    #pragma unroll
    for (int i = 0; i < 4; i++)
        swoff[i] = sw128((uint32_t)(lrow + i * 32) * 128 + (uint32_t)lseg * 16);
    const __half* gA = A  + (size_t)(m0 + lrow) * HDIM + lseg * 8;
    const __half* gB = Wt + (size_t)(n0 + lrow) * HDIM + lseg * 8;

    // ---- hoisted ldmatrix address components ----
    const int arow = wm + ((lane >> 3) & 1) * 8 + (lane & 7);
    const uint32_t mA = ((uint32_t)(arow & 7)) << 4;
    const uint32_t acb = (((lane >> 4) & 1) * 16) ^ (mA & 16u);
    const int brow = wn + ((lane >> 4) & 1) * 8 + (lane & 7);
    const uint32_t mB = ((uint32_t)(brow & 7)) << 4;
    const uint32_t bcb = (((lane >> 3) & 1) * 16) ^ (mB & 16u);
    uint32_t aoff[4], boff[2], ksoA[4], ksoB[4];
    #pragma unroll
    for (int mt = 0; mt < 4; mt++) aoff[mt] = (uint32_t)(arow + mt * 16) * 128 + acb;
    #pragma unroll
    for (int g = 0; g < 2; g++)    boff[g]  = (uint32_t)(brow + g * 16) * 128 + bcb + TILE_BYTES;
    #pragma unroll
    for (int ks = 0; ks < 4; ks++) {
        ksoA[ks] = ((uint32_t)(ks * 32)) ^ (mA & 0x60u);
        ksoB[ks] = ((uint32_t)(ks * 32)) ^ (mB & 0x60u);
    }

    float acc[4][4][4];
    #pragma unroll
    for (int mt = 0; mt < 4; mt++)
        #pragma unroll
        for (int nt = 0; nt < 4; nt++)
            #pragma unroll
            for (int e = 0; e < 4; e++) acc[mt][nt][e] = 0.f;

    // ---- prologue: stages 0,1 ----
    #pragma unroll
    for (int s = 0; s < 2; s++) {
        const uint32_t dst = sbase + s * STAGE_BYTES;
        #pragma unroll
        for (int i = 0; i < 4; i++) {
            cp16(dst + swoff[i],              gA + s * BKH + (size_t)i * 32 * HDIM);
            cp16(dst + TILE_BYTES + swoff[i], gB + s * BKH + (size_t)i * 32 * HDIM);
        }
        CP_COMMIT();
    }

    uint32_t cstage = 0, lstage = 2;
    #pragma unroll 1
    for (int c = 0; c < NCHUNK; c++) {
        CP_WAIT(1);
        __syncthreads();
        if (c + 2 < NCHUNK) {
            const uint32_t dst = sbase + lstage * STAGE_BYTES;
            #pragma unroll
            for (int i = 0; i < 4; i++) {
                cp16(dst + swoff[i],              gA + (c + 2) * BKH + (size_t)i * 32 * HDIM);
                cp16(dst + TILE_BYTES + swoff[i], gB + (c + 2) * BKH + (size_t)i * 32 * HDIM);
            }
            if (++lstage == STAGES) lstage = 0;
            CP_COMMIT();
        } else {
            CP_COMMIT();
        }

        const uint32_t sS = sbase + cstage * STAGE_BYTES;
        #pragma unroll
        for (int ks = 0; ks < 4; ks++) {
            uint32_t bf[2][4];
            ldmx4(sS + boff[0] + ksoB[ks], bf[0]);
            ldmx4(sS + boff[1] + ksoB[ks], bf[1]);
            uint32_t af[4];
            #pragma unroll
            for (int mt = 0; mt < 4; mt++) {
                ldmx4(sS + aoff[mt] + ksoA[ks], af);
                #pragma unroll
                for (int g = 0; g < 2; g++) {
                    mma16816(acc[mt][2 * g],     af, bf[g][0], bf[g][1]);
                    mma16816(acc[mt][2 * g + 1], af, bf[g][2], bf[g][3]);
                }
            }
        }
        if (++cstage == STAGES) cstage = 0;
    }

    // ---- epilogue: bias + tanh.approx -> fp16 ----
    const int qrow = lane >> 2;
    const int qcol = (lane & 3) * 2;
    #pragma unroll
    for (int mt = 0; mt < 4; mt++) {
        const size_t r0 = (size_t)(m0 + wm + mt * 16 + qrow) * HDIM;
        const size_t r1 = r0 + 8 * HDIM;
        #pragma unroll
        for (int nt = 0; nt < 4; nt++) {
            const int col = n0 + wn + nt * 8 + qcol;
            const float b0 = __ldg(bias + col), b1 = __ldg(bias + col + 1);
            *(__half2*)(C + r0 + col) =
                __floats2half2_rn(ftanh(acc[mt][nt][0] + b0), ftanh(acc[mt][nt][1] + b1));
            *(__half2*)(C + r1 + col) =
                __floats2half2_rn(ftanh(acc[mt][nt][2] + b0), ftanh(acc[mt][nt][3] + b1));
        }
    }
}

// =====================================================================
// Kernel 3: neighborhood attention (k=7), uint4 global loads,
//   smem buffer reused for E then V; 2 batches per 512-thread block
// =====================================================================
__global__ __launch_bounds__(512) void agent_attn_kernel(
    const __half2* __restrict__ E2, const __half2* __restrict__ V2,
    float2* __restrict__ out, __half2* __restrict__ outh)
{
    const int hb   = threadIdx.x >> 8;          // which batch half (0/1)
    const int t    = threadIdx.x & 255;
    const int b    = blockIdx.x * 2 + hb;
    __shared__ float2 sE[2][NNEIGH * HDIM2];    // 28KB (E, then reused for V)
    __shared__ float2 q[2][HDIM2];              // 4KB
    __shared__ float  sc[2][8], p[2][8];

    const size_t base2 = (size_t)b * NNEIGH * HDIM2;    // in half2 units
    // ---- load E via 16B loads: 7*256 half2 = 448 uint4 ----
    {
        const uint4* E4 = (const uint4*)(E2 + base2);
        for (int i = t; i < 448; i += 256) {
            uint4 v = E4[i];
            const __half2* h = (const __half2*)&v;
            float2* d = &sE[hb][i * 4];
            d[0] = __half22float2(h[0]); d[1] = __half22float2(h[1]);
            d[2] = __half22float2(h[2]); d[3] = __half22float2(h[3]);
        }
    }
    __syncthreads();

    {
        float2 s = make_float2(0.f, 0.f);
        #pragma unroll
        for (int n = 0; n < NNEIGH; n++) {
            float2 e = sE[hb][n * HDIM2 + t];
            s.x += e.x; s.y += e.y;
        }
        q[hb][t] = make_float2(s.x * (1.f / 7.f), s.y * (1.f / 7.f));
    }
    __syncthreads();

    const int w = t >> 5, lane = t & 31;
    if (w < NNEIGH) {
        float s = 0.f;
        #pragma unroll
        for (int i = lane; i < HDIM2; i += 32) {
            float2 qq = q[hb][i], e = sE[hb][w * HDIM2 + i];
            s += qq.x * e.x + qq.y * e.y;
        }
        #pragma unroll
        for (int o = 16; o > 0; o >>= 1) s += __shfl_xor_sync(0xffffffffu, s, o);
        if (lane == 0) sc[hb][w] = s * 0.04419417382415922f;   // 1/sqrt(512)
    }
    __syncthreads();   // all reads of sE (scores) done

    // ---- overlap: softmax (t==0) + V load into sE (all threads) ----
    if (t == 0) {
        float m = sc[hb][0];
        #pragma unroll
        for (int n = 1; n < NNEIGH; n++) m = fmaxf(m, sc[hb][n]);
        float ssum = 0.f;
        #pragma unroll
        for (int n = 0; n < NNEIGH; n++) { p[hb][n] = __expf(sc[hb][n] - m); ssum += p[hb][n]; }
        float inv = 1.f / ssum;
        #pragma unroll
        for (int n = 0; n < NNEIGH; n++) p[hb][n] *= inv;
    }
    {
        const uint4* V4 = (const uint4*)(V2 + base2);
        for (int i = t; i < 448; i += 256) {
            uint4 v = V4[i];
            const __half2* h = (const __half2*)&v;
            float2* d = &sE[hb][i * 4];
            d[0] = __half22float2(h[0]); d[1] = __half22float2(h[1]);
            d[2] = __half22float2(h[2]); d[3] = __half22float2(h[3]);
        }
    }
    __syncthreads();

    {
        float2 s = make_float2(0.f, 0.f);
        #pragma unroll
        for (int n = 0; n < NNEIGH; n++) {
            float2 v = sE[hb][n * HDIM2 + t];
            s.x += p[hb][n] * v.x; s.y += p[hb][n] * v.y;
        }
        out [(size_t)b * HDIM2 + t] = s;
        outh[(size_t)b * HDIM2 + t] = __float22half2_rn(s);
    }
}

// =====================================================================
// Kernel 4: per-group multi-head attention (8 heads x 64, k=8),
//   uint4 global loads, smem buffer reused for A then V
// =====================================================================
__global__ __launch_bounds__(256) void multi_attn_kernel(
    const __half2* __restrict__ A2, const __half2* __restrict__ V2,
    float2* __restrict__ out)
{
    const int g = blockIdx.x;
    const int t = threadIdx.x;
    __shared__ float2 sA[8 * HDIM2];   // 16KB (A, then reused for V)
    __shared__ float2 q[HDIM2];
    __shared__ float p[8][8];

    const size_t base2 = (size_t)g * 8 * HDIM2;   // half2 units
    // ---- load A via 16B loads: 8*256 half2 = 512 uint4 ----
    {
        const uint4* A4 = (const uint4*)(A2 + base2);
        #pragma unroll
        for (int i = t; i < 512; i += 256) {
            uint4 v = A4[i];
            const __half2* h = (const __half2*)&v;
            float2* d = &sA[i * 4];
            d[0] = __half22float2(h[0]); d[1] = __half22float2(h[1]);
            d[2] = __half22float2(h[2]); d[3] = __half22float2(h[3]);
        }
    }
    __syncthreads();

    {
        float2 s = make_float2(0.f, 0.f);
        #pragma unroll
        for (int a = 0; a < 8; a++) {
            float2 e = sA[a * HDIM2 + t];
            s.x += e.x; s.y += e.y;
        }
        q[t] = make_float2(s.x * 0.125f, s.y * 0.125f);
    }
    __syncthreads();

    const int h = t >> 5, lane = t & 31;
    {
        const int a = lane & 7;
        float s = 0.f;
        #pragma unroll
        for (int i = 0; i < 32; i++) {
            const int idx = h * 32 + i;
            float2 qq = q[idx], e = sA[a * HDIM2 + idx];
            s += qq.x * e.x + qq.y * e.y;
        }
        s *= 0.125f;               // 1/sqrt(64)
        float m = s;
        #pragma unroll
        for (int o = 4; o > 0; o >>= 1) m = fmaxf(m, __shfl_xor_sync(0xffffffffu, m, o, 8));
        float e = __expf(s - m);
        float ssum = e;
        #pragma unroll
        for (int o = 4; o > 0; o >>= 1) ssum += __shfl_xor_sync(0xffffffffu, ssum, o, 8);
        if (lane < 8) p[h][lane] = e / ssum;
    }
    __syncthreads();   // all reads of sA (scores) done; p written

    // ---- reload V into sA (16B loads) ----
    {
        const uint4* V4 = (const uint4*)(V2 + base2);
        #pragma unroll
        for (int i = t; i < 512; i += 256) {
            uint4 v = V4[i];
            const __half2* hh2 = (const __half2*)&v;
            float2* d = &sA[i * 4];
            d[0] = __half22float2(hh2[0]); d[1] = __half22float2(hh2[1]);
            d[2] = __half22float2(hh2[2]); d[3] = __half22float2(hh2[3]);
        }
    }
    __syncthreads();

    {
        const int hh = t >> 5;
        float2 s = make_float2(0.f, 0.f);
        #pragma unroll
        for (int a = 0; a < 8; a++) {
            float2 v = sA[a * HDIM2 + t];
            s.x += p[hh][a] * v.x; s.y += p[hh][a] * v.y;
        }
        #pragma unroll
        for (int rep = 0; rep < 8; rep++)
            out[((size_t)rep * NGROUPS + g) * HDIM2 + t] = s;
    }
}

// =====================================================================
// launch
// =====================================================================
extern "C" void kernel_launch(void* const* d_in, const int* in_sizes, int n_in,
                              void* d_out, int out_size)
{
    const float* self_obs = (const float*)d_in[0];
    const float* obs      = (const float*)d_in[1];
    const float* W_e1 = (const float*)d_in[2];  const float* b_e1 = (const float*)d_in[3];
    const float* W_e2 = (const float*)d_in[4];  const float* b_e2 = (const float*)d_in[5];
    const float* W_n1 = (const float*)d_in[6];  const float* b_n1 = (const float*)d_in[7];
    const float* W_n2 = (const float*)d_in[8];  const float* b_n2 = (const float*)d_in[9];
    const float* W_a1 = (const float*)d_in[10]; const float* b_a1 = (const float*)d_in[11];
    const float* W_a2 = (const float*)d_in[12]; const float* b_a2 = (const float*)d_in[13];

    float* out      = (float*)d_out;
    float* agentatt = out + OUT_HALF;

    __half *p_h1, *p_E, *p_V, *p_aa, *p_ah, *p_av, *p_Wt, *p_Wt1;
    cudaGetSymbolAddress((void**)&p_h1, g_h1h);
    cudaGetSymbolAddress((void**)&p_E,  g_Eh);
    cudaGetSymbolAddress((void**)&p_V,  g_Vh);
    cudaGetSymbolAddress((void**)&p_aa, g_aah);
    cudaGetSymbolAddress((void**)&p_ah, g_ahh);
    cudaGetSymbolAddress((void**)&p_av, g_avh);
    cudaGetSymbolAddress((void**)&p_Wt, g_Wt);
    cudaGetSymbolAddress((void**)&p_Wt1, g_Wt1);

    __half* Wt_e2 = p_Wt + 0 * (size_t)HDIM * HDIM;
    __half* Wt_n1 = p_Wt + 1 * (size_t)HDIM * HDIM;
    __half* Wt_n2 = p_Wt + 2 * (size_t)HDIM * HDIM;
    __half* Wt_a1 = p_Wt + 3 * (size_t)HDIM * HDIM;
    __half* Wt_a2 = p_Wt + 4 * (size_t)HDIM * HDIM;

    cudaFuncSetAttribute(gemm_hmma, cudaFuncAttributeMaxDynamicSharedMemorySize, GEMM_SMEM);

    // weight prep (1 launch: 5 transposes + W_e1 pad)
    prep_weights_kernel<<<dim3(16, 16, 6), dim3(32, 8)>>>(
        W_e2, W_n1, W_n2, W_a1, W_a2, p_Wt, W_e1, p_Wt1);

    // 1) h1 = tanh(gathered @ W_e1 + b_e1)   (HMMA, K=32 padded)
    embed1_hmma<<<dim3(4, MROWS / BM), 256>>>(self_obs, obs, p_Wt1, b_e1, p_h1);
    // 2-4) big GEMMs (grid: n fast for L2 A-reuse)
    gemm_hmma<<<dim3(4, MROWS / BM), 256, GEMM_SMEM>>>(p_h1, Wt_e2, b_e2, p_E);
    gemm_hmma<<<dim3(4, MROWS / BM), 256, GEMM_SMEM>>>(p_E,  Wt_n1, b_n1, p_h1);
    gemm_hmma<<<dim3(4, MROWS / BM), 256, GEMM_SMEM>>>(p_h1, Wt_n2, b_n2, p_V);
    // 5) neighborhood attention -> agent_attention (fp32 to d_out + fp16 copy)
    agent_attn_kernel<<<B_SZ / 2, 512>>>(
        (const __half2*)p_E, (const __half2*)p_V,
        (float2*)agentatt, (__half2*)p_aa);
    // 6-7) agent MLP
    gemm_hmma<<<dim3(4, B_SZ / BM), 256, GEMM_SMEM>>>(p_aa, Wt_a1, b_a1, p_ah);
    gemm_hmma<<<dim3(4, B_SZ / BM), 256, GEMM_SMEM>>>(p_ah, Wt_a2, b_a2, p_av);
    // 8) multi-head attention -> first half of d_out (x8 tiled)
    multi_attn_kernel<<<NGROUPS, 256>>>(
        (const __half2*)p_aa, (const __half2*)p_av, (float2*)out);
}

// round 14
// speedup vs baseline: 1.1130x; 1.0411x over previous
#include <cuda_runtime.h>
#include <cuda_fp16.h>
#include <cstdint>

// ---------------- problem constants ----------------
#define B_SZ     16384
#define NNEIGH   7
#define HDIM     512
#define HDIM2    256                   // HDIM in half2/float2 units
#define MROWS    (B_SZ * NNEIGH)      // 114688
#define SELF_W   18
#define NEIGH_W  6
#define OBS_W    (SELF_W + NEIGH_W * NNEIGH)  // 60
#define NGROUPS  (B_SZ / 8)           // 2048
#define OUT_HALF ((size_t)B_SZ * HDIM)

// GEMM tiling (128x128, warp 64x32, 2 CTAs/SM, 3 stages)
#define BM   128
#define BN   128
#define BKH  64                        // halves per K chunk (128 bytes/row)
#define NCHUNK (HDIM / BKH)            // 8
#define TILE_BYTES (BM * BKH * 2)      // 16384
#define STAGE_BYTES (2 * TILE_BYTES)   // A+B per stage = 32768
#define STAGES 3
#define GEMM_SMEM (STAGES * STAGE_BYTES + 64)  // 96KB + barrier space

// ---------------- scratch (__device__ globals; no allocs allowed) ---------
__device__ __half g_h1h[(size_t)MROWS * HDIM];
__device__ __half g_Eh [(size_t)MROWS * HDIM];
__device__ __half g_Vh [(size_t)MROWS * HDIM];
__device__ __half g_aah[(size_t)B_SZ * HDIM];
__device__ __half g_ahh[(size_t)B_SZ * HDIM];
__device__ __half g_avh[(size_t)B_SZ * HDIM];
__device__ __half g_Wt [5 * (size_t)HDIM * HDIM];
__device__ __half g_Wt1[(size_t)HDIM * 32];     // W_e1^T padded to K=32

// ---------------- small helpers ----------------
__device__ __forceinline__ uint32_t smem_u32(const void* p) {
    uint32_t a;
    asm("{ .reg .u64 t; cvta.to.shared.u64 t, %1; cvt.u32.u64 %0, t; }" : "=r"(a) : "l"(p));
    return a;
}
__device__ __forceinline__ void cp16(uint32_t s, const void* g) {
    asm volatile("cp.async.cg.shared.global [%0], [%1], 16;" :: "r"(s), "l"(g));
}
#define CP_COMMIT()  asm volatile("cp.async.commit_group;" ::: "memory")
#define CP_WAIT(n)   asm volatile("cp.async.wait_group %0;" :: "n"(n) : "memory")

// mbarrier ops (Hopper+, valid on sm_100 target)
#define MBAR_INIT(a, c) \
    asm volatile("mbarrier.init.shared.b64 [%0], %1;" :: "r"((uint32_t)(a)), "r"((uint32_t)(c)) : "memory")
#define MBAR_ARRIVE(a) \
    asm volatile("mbarrier.arrive.shared.b64 _, [%0];" :: "r"((uint32_t)(a)) : "memory")
#define CP_MBAR_ARRIVE(a) \
    asm volatile("cp.async.mbarrier.arrive.noinc.shared.b64 [%0];" :: "r"((uint32_t)(a)) : "memory")
#define MBAR_WAIT(a, ph) \
    asm volatile("{\n\t.reg .pred P;\n\t" \
        "WAITLP_%=:\n\t" \
        "mbarrier.try_wait.parity.acquire.cta.shared::cta.b64 P, [%0], %1;\n\t" \
        "@!P bra WAITLP_%=;\n\t}" \
        :: "r"((uint32_t)(a)), "r"((uint32_t)(ph)) : "memory")

__device__ __forceinline__ void ldmx4(uint32_t addr, uint32_t* r) {
    asm volatile("ldmatrix.sync.aligned.m8n8.x4.shared.b16 {%0,%1,%2,%3}, [%4];"
        : "=r"(r[0]), "=r"(r[1]), "=r"(r[2]), "=r"(r[3]) : "r"(addr));
}
__device__ __forceinline__ void mma16816(float* c, const uint32_t* a, uint32_t b0, uint32_t b1) {
    asm volatile("mma.sync.aligned.m16n8k16.row.col.f32.f16.f16.f32 "
        "{%0,%1,%2,%3},{%4,%5,%6,%7},{%8,%9},{%0,%1,%2,%3};"
        : "+f"(c[0]), "+f"(c[1]), "+f"(c[2]), "+f"(c[3])
        : "r"(a[0]), "r"(a[1]), "r"(a[2]), "r"(a[3]), "r"(b0), "r"(b1));
}
__device__ __forceinline__ uint32_t sw128(uint32_t off) {   // SW128 swizzle
    return off ^ ((off >> 3) & 0x70);
}
// single-MUFU tanh (sm_75+); max rel err ~2^-11 == fp16 quantization scale
__device__ __forceinline__ float ftanh(float x) {
    float r;
    asm("tanh.approx.f32 %0, %1;" : "=f"(r) : "f"(x));
    return r;
}

// =====================================================================
// Weight prep: 5 transposes (z=0..4) + W_e1 pad/transpose (z=5)
// =====================================================================
__global__ __launch_bounds__(256) void prep_weights_kernel(
    const float* __restrict__ W0, const float* __restrict__ W1,
    const float* __restrict__ W2, const float* __restrict__ W3,
    const float* __restrict__ W4, __half* __restrict__ WtBase,
    const float* __restrict__ We1, __half* __restrict__ Wt1)
{
    __shared__ float t[32][33];
    if (blockIdx.z == 5) {
        const int ftid = threadIdx.y * 32 + threadIdx.x;
        const int idx = (blockIdx.y * 16 + blockIdx.x) * 256 + ftid;
        if (idx < HDIM * 32) {
            const int n = idx >> 5, k = idx & 31;
            Wt1[idx] = (k < 24) ? __float2half(We1[(size_t)k * HDIM + n]) : __half(0.f);
        }
        return;
    }
    const float* W;
    switch (blockIdx.z) {
        case 0: W = W0; break;
        case 1: W = W1; break;
        case 2: W = W2; break;
        case 3: W = W3; break;
        default: W = W4; break;
    }
    __half* Wt = WtBase + (size_t)blockIdx.z * HDIM * HDIM;
    const int bx = blockIdx.x * 32, by = blockIdx.y * 32;
    #pragma unroll
    for (int i = threadIdx.y; i < 32; i += 8)
        t[i][threadIdx.x] = W[(size_t)(by + i) * HDIM + bx + threadIdx.x];
    __syncthreads();
    #pragma unroll
    for (int i = threadIdx.y; i < 32; i += 8)
        Wt[(size_t)(bx + i) * HDIM + by + threadIdx.x] = __float2half(t[threadIdx.x][i]);
}

// =====================================================================
// Kernel 1: fused gather + HMMA GEMM (K=24 pad 32) + bias + tanh -> fp16
// =====================================================================
__global__ __launch_bounds__(256) void embed1_hmma(
    const float* __restrict__ self_obs, const float* __restrict__ obs,
    const __half* __restrict__ Wt1, const float* __restrict__ bias,
    __half* __restrict__ C)
{
    __shared__ __align__(128) unsigned char sm[2 * 16384];  // A, B (128 rows x 128B)
    const uint32_t sbase = smem_u32(sm);
    const int tid  = threadIdx.x;
    const int wid  = tid >> 5, lane = tid & 31;
    const int n0   = blockIdx.x * BN;
    const int m0   = blockIdx.y * BM;
    const int wm   = (wid >> 2) * 64;
    const int wn   = (wid & 3) * 32;

    // ---- fill tiles: each thread 1 half-row (32B = 16 halves) ----
    const int row = tid >> 1, seg = tid & 1;
    {
        const int j = m0 + row;
        const int sb = (j % B_SZ) * SELF_W;
        const int ob = (j / NNEIGH) * OBS_W + SELF_W + (j % NNEIGH) * NEIGH_W;
        __half vals[16];
        #pragma unroll
        for (int c = 0; c < 16; c++) {
            const int k = seg * 16 + c;
            float v = 0.f;
            if (k < SELF_W)      v = __ldg(self_obs + sb + k);
            else if (k < 24)     v = __ldg(obs + ob + (k - SELF_W));
            vals[c] = __float2half(v);
        }
        const uint32_t base = (uint32_t)row * 128 + (uint32_t)seg * 32;
        *(uint4*)(sm + sw128(base))      = ((const uint4*)vals)[0];
        *(uint4*)(sm + sw128(base + 16)) = ((const uint4*)vals)[1];
        const __half* bsrc = Wt1 + (size_t)(n0 + row) * 32 + seg * 16;
        *(uint4*)(sm + 16384 + sw128(base))      = *(const uint4*)bsrc;
        *(uint4*)(sm + 16384 + sw128(base + 16)) = *(const uint4*)(bsrc + 8);
    }
    __syncthreads();

    const int arow = wm + ((lane >> 3) & 1) * 8 + (lane & 7);
    const uint32_t acolbase = ((lane >> 4) & 1) * 16;
    const int brow = wn + ((lane >> 4) & 1) * 8 + (lane & 7);
    const uint32_t bcolbase = ((lane >> 3) & 1) * 16;

    float acc[4][4][4];
    #pragma unroll
    for (int mt = 0; mt < 4; mt++)
        #pragma unroll
        for (int nt = 0; nt < 4; nt++)
            #pragma unroll
            for (int e = 0; e < 4; e++) acc[mt][nt][e] = 0.f;

    const uint32_t sA = sbase, sB = sbase + 16384;
    #pragma unroll
    for (int ks = 0; ks < 2; ks++) {
        uint32_t bf[2][4];
        #pragma unroll
        for (int g = 0; g < 2; g++) {
            int r = brow + g * 16;
            uint32_t col = (bcolbase + ks * 32) ^ (((uint32_t)(r & 7)) << 4);
            ldmx4(sB + (uint32_t)r * 128 + col, bf[g]);
        }
        uint32_t af[4];
        #pragma unroll
        for (int mt = 0; mt < 4; mt++) {
            int r = arow + mt * 16;
            uint32_t col = (acolbase + ks * 32) ^ (((uint32_t)(r & 7)) << 4);
            ldmx4(sA + (uint32_t)r * 128 + col, af);
            #pragma unroll
            for (int g = 0; g < 2; g++) {
                mma16816(acc[mt][2 * g],     af, bf[g][0], bf[g][1]);
                mma16816(acc[mt][2 * g + 1], af, bf[g][2], bf[g][3]);
            }
        }
    }

    const int qrow = lane >> 2;
    const int qcol = (lane & 3) * 2;
    #pragma unroll
    for (int mt = 0; mt < 4; mt++) {
        const size_t r0 = (size_t)(m0 + wm + mt * 16 + qrow) * HDIM;
        const size_t r1 = r0 + 8 * HDIM;
        #pragma unroll
        for (int nt = 0; nt < 4; nt++) {
            const int col = n0 + wn + nt * 8 + qcol;
            const float b0 = __ldg(bias + col), b1 = __ldg(bias + col + 1);
            *(__half2*)(C + r0 + col) =
                __floats2half2_rn(ftanh(acc[mt][nt][0] + b0), ftanh(acc[mt][nt][1] + b1));
            *(__half2*)(C + r1 + col) =
                __floats2half2_rn(ftanh(acc[mt][nt][2] + b0), ftanh(acc[mt][nt][3] + b1));
        }
    }
}

// =====================================================================
// Kernel 2: HMMA fp16 GEMM with mbarrier producer/consumer ring
//   (decouples warps + co-resident CTAs at chunk boundaries)
//   C = (half) tanh(A @ Wt^T + bias); grid (4, m_blocks)
// =====================================================================
__global__ __launch_bounds__(256, 2) void gemm_hmma(
    const __half* __restrict__ A, const __half* __restrict__ Wt,
    const float* __restrict__ bias, __half* __restrict__ C)
{
    extern __shared__ __align__(16) unsigned char smem[];
    const uint32_t sbase = smem_u32(smem);
    const uint32_t mb    = sbase + STAGES * STAGE_BYTES;   // full(s)=mb+s*16, empty(s)=mb+s*16+8
    const int tid  = threadIdx.x;
    const int wid  = tid >> 5, lane = tid & 31;
    const int n0   = blockIdx.x * BN;
    const int m0   = blockIdx.y * BM;
    const int wm   = (wid >> 2) * 64;
    const int wn   = (wid & 3) * 32;

    if (tid == 0) {
        #pragma unroll
        for (int s = 0; s < STAGES; s++) {
            MBAR_INIT(mb + s * 16,     256);   // full: 256 cp.async completions
            MBAR_INIT(mb + s * 16 + 8, 256);   // empty: 256 consumer arrivals
        }
    }
    __syncthreads();

    // ---- cp.async loader mapping (swizzle invariant under +i*4096) ----
    const int lrow = tid >> 3, lseg = tid & 7;
    const uint32_t swz = sw128((uint32_t)lrow * 128 + (uint32_t)lseg * 16);
    const __half* gA = A  + (size_t)(m0 + lrow) * HDIM + lseg * 8;
    const __half* gB = Wt + (size_t)(n0 + lrow) * HDIM + lseg * 8;

    // ---- hoisted ldmatrix address components ----
    const int arow = wm + ((lane >> 3) & 1) * 8 + (lane & 7);
    const uint32_t mA = ((uint32_t)(arow & 7)) << 4;
    const uint32_t mAhi = mA & 0x60u;
    const uint32_t acb = (((lane >> 4) & 1) * 16) ^ (mA & 16u);
    const int brow = wn + ((lane >> 4) & 1) * 8 + (lane & 7);
    const uint32_t mB = ((uint32_t)(brow & 7)) << 4;
    const uint32_t mBhi = mB & 0x60u;
    const uint32_t bcb = (((lane >> 3) & 1) * 16) ^ (mB & 16u);
    uint32_t aoff[4], boff[2];
    #pragma unroll
    for (int mt = 0; mt < 4; mt++) aoff[mt] = (uint32_t)(arow + mt * 16) * 128 + acb;
    #pragma unroll
    for (int g = 0; g < 2; g++)    boff[g]  = (uint32_t)(brow + g * 16) * 128 + bcb + TILE_BYTES;

    float acc[4][4][4];
    #pragma unroll
    for (int mt = 0; mt < 4; mt++)
        #pragma unroll
        for (int nt = 0; nt < 4; nt++)
            #pragma unroll
            for (int e = 0; e < 4; e++) acc[mt][nt][e] = 0.f;

    int pstage = 0, pphase = 1;       // producer cursor (phase flipped: first waits pass)
    int cstage = 0, cphase = 0;       // consumer cursor

    // ---- prologue: load chunks 0,1 ----
    #pragma unroll
    for (int k = 0; k < 2; k++) {
        MBAR_WAIT(mb + pstage * 16 + 8, pphase);     // passes immediately
        const uint32_t dst = sbase + pstage * STAGE_BYTES + swz;
        #pragma unroll
        for (int i = 0; i < 4; i++) {
            cp16(dst + (uint32_t)i * 4096,              gA + k * BKH + (size_t)i * 32 * HDIM);
            cp16(dst + TILE_BYTES + (uint32_t)i * 4096, gB + k * BKH + (size_t)i * 32 * HDIM);
        }
        CP_MBAR_ARRIVE(mb + pstage * 16);
        if (++pstage == STAGES) { pstage = 0; pphase ^= 1; }
    }

    #pragma unroll 1
    for (int c = 0; c < NCHUNK; c++) {
        // ---- producer: load chunk c+2 (buffer freed by consumer one lap back) ----
        if (c + 2 < NCHUNK) {
            MBAR_WAIT(mb + pstage * 16 + 8, pphase);
            const uint32_t dst = sbase + pstage * STAGE_BYTES + swz;
            #pragma unroll
            for (int i = 0; i < 4; i++) {
                cp16(dst + (uint32_t)i * 4096,              gA + (c + 2) * BKH + (size_t)i * 32 * HDIM);
                cp16(dst + TILE_BYTES + (uint32_t)i * 4096, gB + (c + 2) * BKH + (size_t)i * 32 * HDIM);
            }
            CP_MBAR_ARRIVE(mb + pstage * 16);
            if (++pstage == STAGES) { pstage = 0; pphase ^= 1; }
        }

        // ---- consumer: wait data, MMA, release buffer ----
        MBAR_WAIT(mb + cstage * 16, cphase);
        const uint32_t sS = sbase + cstage * STAGE_BYTES;
        #pragma unroll
        for (int ks = 0; ks < 4; ks++) {
            const uint32_t koA = ((uint32_t)(ks * 32)) ^ mAhi;
            const uint32_t koB = ((uint32_t)(ks * 32)) ^ mBhi;
            uint32_t bf[2][4];
            ldmx4(sS + boff[0] + koB, bf[0]);
            ldmx4(sS + boff[1] + koB, bf[1]);
            uint32_t af[4];
            #pragma unroll
            for (int mt = 0; mt < 4; mt++) {
                ldmx4(sS + aoff[mt] + koA, af);
                #pragma unroll
                for (int g = 0; g < 2; g++) {
                    mma16816(acc[mt][2 * g],     af, bf[g][0], bf[g][1]);
                    mma16816(acc[mt][2 * g + 1], af, bf[g][2], bf[g][3]);
                }
            }
        }
        MBAR_ARRIVE(mb + cstage * 16 + 8);
        if (++cstage == STAGES) { cstage = 0; cphase ^= 1; }
    }

    // ---- epilogue: bias + tanh.approx -> fp16 ----
    const int qrow = lane >> 2;
    const int qcol = (lane & 3) * 2;
    #pragma unroll
    for (int mt = 0; mt < 4; mt++) {
        const size_t r0 = (size_t)(m0 + wm + mt * 16 + qrow) * HDIM;
        const size_t r1 = r0 + 8 * HDIM;
        #pragma unroll
        for (int nt = 0; nt < 4; nt++) {
            const int col = n0 + wn + nt * 8 + qcol;
            const float b0 = __ldg(bias + col), b1 = __ldg(bias + col + 1);
            *(__half2*)(C + r0 + col) =
                __floats2half2_rn(ftanh(acc[mt][nt][0] + b0), ftanh(acc[mt][nt][1] + b1));
            *(__half2*)(C + r1 + col) =
                __floats2half2_rn(ftanh(acc[mt][nt][2] + b0), ftanh(acc[mt][nt][3] + b1));
        }
    }
}

// =====================================================================
// Kernel 3: neighborhood attention (k=7), uint4 global loads,
//   smem buffer reused for E then V; 2 batches per 512-thread block
// =====================================================================
__global__ __launch_bounds__(512) void agent_attn_kernel(
    const __half2* __restrict__ E2, const __half2* __restrict__ V2,
    float2* __restrict__ out, __half2* __restrict__ outh)
{
    const int hb   = threadIdx.x >> 8;          // which batch half (0/1)
    const int t    = threadIdx.x & 255;
    const int b    = blockIdx.x * 2 + hb;
    __shared__ float2 sE[2][NNEIGH * HDIM2];    // 28KB (E, then reused for V)
    __shared__ float2 q[2][HDIM2];              // 4KB
    __shared__ float  sc[2][8], p[2][8];

    const size_t base2 = (size_t)b * NNEIGH * HDIM2;    // in half2 units
    {
        const uint4* E4 = (const uint4*)(E2 + base2);
        for (int i = t; i < 448; i += 256) {
            uint4 v = E4[i];
            const __half2* h = (const __half2*)&v;
            float2* d = &sE[hb][i * 4];
            d[0] = __half22float2(h[0]); d[1] = __half22float2(h[1]);
            d[2] = __half22float2(h[2]); d[3] = __half22float2(h[3]);
        }
    }
    __syncthreads();

    {
        float2 s = make_float2(0.f, 0.f);
        #pragma unroll
        for (int n = 0; n < NNEIGH; n++) {
            float2 e = sE[hb][n * HDIM2 + t];
            s.x += e.x; s.y += e.y;
        }
        q[hb][t] = make_float2(s.x * (1.f / 7.f), s.y * (1.f / 7.f));
    }
    __syncthreads();

    const int w = t >> 5, lane = t & 31;
    if (w < NNEIGH) {
        float s = 0.f;
        #pragma unroll
        for (int i = lane; i < HDIM2; i += 32) {
            float2 qq = q[hb][i], e = sE[hb][w * HDIM2 + i];
            s += qq.x * e.x + qq.y * e.y;
        }
        #pragma unroll
        for (int o = 16; o > 0; o >>= 1) s += __shfl_xor_sync(0xffffffffu, s, o);
        if (lane == 0) sc[hb][w] = s * 0.04419417382415922f;   // 1/sqrt(512)
    }
    __syncthreads();   // all reads of sE (scores) done

    if (t == 0) {
        float m = sc[hb][0];
        #pragma unroll
        for (int n = 1; n < NNEIGH; n++) m = fmaxf(m, sc[hb][n]);
        float ssum = 0.f;
        #pragma unroll
        for (int n = 0; n < NNEIGH; n++) { p[hb][n] = __expf(sc[hb][n] - m); ssum += p[hb][n]; }
        float inv = 1.f / ssum;
        #pragma unroll
        for (int n = 0; n < NNEIGH; n++) p[hb][n] *= inv;
    }
    {
        const uint4* V4 = (const uint4*)(V2 + base2);
        for (int i = t; i < 448; i += 256) {
            uint4 v = V4[i];
            const __half2* h = (const __half2*)&v;
            float2* d = &sE[hb][i * 4];
            d[0] = __half22float2(h[0]); d[1] = __half22float2(h[1]);
            d[2] = __half22float2(h[2]); d[3] = __half22float2(h[3]);
        }
    }
    __syncthreads();

    {
        float2 s = make_float2(0.f, 0.f);
        #pragma unroll
        for (int n = 0; n < NNEIGH; n++) {
            float2 v = sE[hb][n * HDIM2 + t];
            s.x += p[hb][n] * v.x; s.y += p[hb][n] * v.y;
        }
        out [(size_t)b * HDIM2 + t] = s;
        outh[(size_t)b * HDIM2 + t] = __float22half2_rn(s);
    }
}

// =====================================================================
// Kernel 4: per-group multi-head attention (8 heads x 64, k=8),
//   uint4 global loads, smem buffer reused for A then V
// =====================================================================
__global__ __launch_bounds__(256) void multi_attn_kernel(
    const __half2* __restrict__ A2, const __half2* __restrict__ V2,
    float2* __restrict__ out)
{
    const int g = blockIdx.x;
    const int t = threadIdx.x;
    __shared__ float2 sA[8 * HDIM2];   // 16KB (A, then reused for V)
    __shared__ float2 q[HDIM2];
    __shared__ float p[8][8];

    const size_t base2 = (size_t)g * 8 * HDIM2;   // half2 units
    {
        const uint4* A4 = (const uint4*)(A2 + base2);
        #pragma unroll
        for (int i = t; i < 512; i += 256) {
            uint4 v = A4[i];
            const __half2* h = (const __half2*)&v;
            float2* d = &sA[i * 4];
            d[0] = __half22float2(h[0]); d[1] = __half22float2(h[1]);
            d[2] = __half22float2(h[2]); d[3] = __half22float2(h[3]);
        }
    }
    __syncthreads();

    {
        float2 s = make_float2(0.f, 0.f);
        #pragma unroll
        for (int a = 0; a < 8; a++) {
            float2 e = sA[a * HDIM2 + t];
            s.x += e.x; s.y += e.y;
        }
        q[t] = make_float2(s.x * 0.125f, s.y * 0.125f);
    }
    __syncthreads();

    const int h = t >> 5, lane = t & 31;
    {
        const int a = lane & 7;
        float s = 0.f;
        #pragma unroll
        for (int i = 0; i < 32; i++) {
            const int idx = h * 32 + i;
            float2 qq = q[idx], e = sA[a * HDIM2 + idx];
            s += qq.x * e.x + qq.y * e.y;
        }
        s *= 0.125f;               // 1/sqrt(64)
        float m = s;
        #pragma unroll
        for (int o = 4; o > 0; o >>= 1) m = fmaxf(m, __shfl_xor_sync(0xffffffffu, m, o, 8));
        float e = __expf(s - m);
        float ssum = e;
        #pragma unroll
        for (int o = 4; o > 0; o >>= 1) ssum += __shfl_xor_sync(0xffffffffu, ssum, o, 8);
        if (lane < 8) p[h][lane] = e / ssum;
    }
    __syncthreads();   // all reads of sA (scores) done; p written

    {
        const uint4* V4 = (const uint4*)(V2 + base2);
        #pragma unroll
        for (int i = t; i < 512; i += 256) {
            uint4 v = V4[i];
            const __half2* hh2 = (const __half2*)&v;
            float2* d = &sA[i * 4];
            d[0] = __half22float2(hh2[0]); d[1] = __half22float2(hh2[1]);
            d[2] = __half22float2(hh2[2]); d[3] = __half22float2(hh2[3]);
        }
    }
    __syncthreads();

    {
        const int hh = t >> 5;
        float2 s = make_float2(0.f, 0.f);
        #pragma unroll
        for (int a = 0; a < 8; a++) {
            float2 v = sA[a * HDIM2 + t];
            s.x += p[hh][a] * v.x; s.y += p[hh][a] * v.y;
        }
        #pragma unroll
        for (int rep = 0; rep < 8; rep++)
            out[((size_t)rep * NGROUPS + g) * HDIM2 + t] = s;
    }
}

// =====================================================================
// launch
// =====================================================================
extern "C" void kernel_launch(void* const* d_in, const int* in_sizes, int n_in,
                              void* d_out, int out_size)
{
    const float* self_obs = (const float*)d_in[0];
    const float* obs      = (const float*)d_in[1];
    const float* W_e1 = (const float*)d_in[2];  const float* b_e1 = (const float*)d_in[3];
    const float* W_e2 = (const float*)d_in[4];  const float* b_e2 = (const float*)d_in[5];
    const float* W_n1 = (const float*)d_in[6];  const float* b_n1 = (const float*)d_in[7];
    const float* W_n2 = (const float*)d_in[8];  const float* b_n2 = (const float*)d_in[9];
    const float* W_a1 = (const float*)d_in[10]; const float* b_a1 = (const float*)d_in[11];
    const float* W_a2 = (const float*)d_in[12]; const float* b_a2 = (const float*)d_in[13];

    float* out      = (float*)d_out;
    float* agentatt = out + OUT_HALF;

    __half *p_h1, *p_E, *p_V, *p_aa, *p_ah, *p_av, *p_Wt, *p_Wt1;
    cudaGetSymbolAddress((void**)&p_h1, g_h1h);
    cudaGetSymbolAddress((void**)&p_E,  g_Eh);
    cudaGetSymbolAddress((void**)&p_V,  g_Vh);
    cudaGetSymbolAddress((void**)&p_aa, g_aah);
    cudaGetSymbolAddress((void**)&p_ah, g_ahh);
    cudaGetSymbolAddress((void**)&p_av, g_avh);
    cudaGetSymbolAddress((void**)&p_Wt, g_Wt);
    cudaGetSymbolAddress((void**)&p_Wt1, g_Wt1);

    __half* Wt_e2 = p_Wt + 0 * (size_t)HDIM * HDIM;
    __half* Wt_n1 = p_Wt + 1 * (size_t)HDIM * HDIM;
    __half* Wt_n2 = p_Wt + 2 * (size_t)HDIM * HDIM;
    __half* Wt_a1 = p_Wt + 3 * (size_t)HDIM * HDIM;
    __half* Wt_a2 = p_Wt + 4 * (size_t)HDIM * HDIM;

    cudaFuncSetAttribute(gemm_hmma, cudaFuncAttributeMaxDynamicSharedMemorySize, GEMM_SMEM);

    // weight prep (1 launch: 5 transposes + W_e1 pad)
    prep_weights_kernel<<<dim3(16, 16, 6), dim3(32, 8)>>>(
        W_e2, W_n1, W_n2, W_a1, W_a2, p_Wt, W_e1, p_Wt1);

    // 1) h1 = tanh(gathered @ W_e1 + b_e1)   (HMMA, K=32 padded)
    embed1_hmma<<<dim3(4, MROWS / BM), 256>>>(self_obs, obs, p_Wt1, b_e1, p_h1);
    // 2-4) big GEMMs (grid: n fast for L2 A-reuse)
    gemm_hmma<<<dim3(4, MROWS / BM), 256, GEMM_SMEM>>>(p_h1, Wt_e2, b_e2, p_E);
    gemm_hmma<<<dim3(4, MROWS / BM), 256, GEMM_SMEM>>>(p_E,  Wt_n1, b_n1, p_h1);
    gemm_hmma<<<dim3(4, MROWS / BM), 256, GEMM_SMEM>>>(p_h1, Wt_n2, b_n2, p_V);
    // 5) neighborhood attention -> agent_attention (fp32 to d_out + fp16 copy)
    agent_attn_kernel<<<B_SZ / 2, 512>>>(
        (const __half2*)p_E, (const __half2*)p_V,
        (float2*)agentatt, (__half2*)p_aa);
    // 6-7) agent MLP
    gemm_hmma<<<dim3(4, B_SZ / BM), 256, GEMM_SMEM>>>(p_aa, Wt_a1, b_a1, p_ah);
    gemm_hmma<<<dim3(4, B_SZ / BM), 256, GEMM_SMEM>>>(p_ah, Wt_a2, b_a2, p_av);
    // 8) multi-head attention -> first half of d_out (x8 tiled)
    multi_attn_kernel<<<NGROUPS, 256>>>(
        (const __half2*)p_aa, (const __half2*)p_av, (float2*)out);
}